// round 1
// baseline (speedup 1.0000x reference)
#include <cuda_runtime.h>
#include <math.h>
#include <stdint.h>

#define T_SEQ 4096
#define BATCH 2
#define CDIM  1024
#define HD    256
#define NH    4
#define WIN   512
#define PAD   68

// ---------------- scratch (static device globals; no allocation) ----------------
__device__ float g_q [(size_t)BATCH * T_SEQ * CDIM];   // 32 MB
__device__ float g_k [(size_t)BATCH * T_SEQ * HD];     // 8 MB
__device__ float g_v [(size_t)BATCH * T_SEQ * HD];     // 8 MB
__device__ float g_ao[(size_t)BATCH * T_SEQ * CDIM];   // 32 MB

// ---------------- SGEMM: C[M,N] = A[M,K] * B[N,K]^T (all row-major) -------------
__global__ __launch_bounds__(256) void sgemm_nt(
    int M, int N, int K,
    const float* __restrict__ A,
    const float* __restrict__ B,
    float* __restrict__ C)
{
    __shared__ float As[8][128];
    __shared__ float Bs[8][128];

    const int tid = threadIdx.x;
    const int tx = tid & 15;
    const int ty = tid >> 4;
    const int m0 = blockIdx.y << 7;
    const int n0 = blockIdx.x << 7;
    const int lr = tid >> 1;
    const int lk = (tid & 1) << 2;

    const float* Ap = A + (size_t)(m0 + lr) * K + lk;
    const float* Bp = B + (size_t)(n0 + lr) * K + lk;

    float acc[8][8];
#pragma unroll
    for (int i = 0; i < 8; i++)
#pragma unroll
        for (int j = 0; j < 8; j++) acc[i][j] = 0.f;

    for (int k0 = 0; k0 < K; k0 += 8) {
        float4 a4 = *(const float4*)(Ap + k0);
        float4 b4 = *(const float4*)(Bp + k0);
        __syncthreads();
        As[lk + 0][lr] = a4.x; As[lk + 1][lr] = a4.y;
        As[lk + 2][lr] = a4.z; As[lk + 3][lr] = a4.w;
        Bs[lk + 0][lr] = b4.x; Bs[lk + 1][lr] = b4.y;
        Bs[lk + 2][lr] = b4.z; Bs[lk + 3][lr] = b4.w;
        __syncthreads();
#pragma unroll
        for (int kk = 0; kk < 8; kk++) {
            float a[8], b[8];
            *(float4*)&a[0] = *(const float4*)&As[kk][ty * 8];
            *(float4*)&a[4] = *(const float4*)&As[kk][ty * 8 + 4];
            *(float4*)&b[0] = *(const float4*)&Bs[kk][tx * 8];
            *(float4*)&b[4] = *(const float4*)&Bs[kk][tx * 8 + 4];
#pragma unroll
            for (int i = 0; i < 8; i++)
#pragma unroll
                for (int j = 0; j < 8; j++)
                    acc[i][j] = fmaf(a[i], b[j], acc[i][j]);
        }
    }

#pragma unroll
    for (int i = 0; i < 8; i++) {
        float* cp = C + (size_t)(m0 + ty * 8 + i) * N + n0 + tx * 8;
        float4 o0 = make_float4(acc[i][0], acc[i][1], acc[i][2], acc[i][3]);
        float4 o1 = make_float4(acc[i][4], acc[i][5], acc[i][6], acc[i][7]);
        *(float4*)cp       = o0;
        *(float4*)(cp + 4) = o1;
    }
}

// ---------------- fused RMSNorm + RoPE (1 warp per 256-wide head row) ----------
__global__ void rmsnorm_rope(float* __restrict__ buf, const float* __restrict__ gamma,
                             int nrows, int heads)
{
    int gw   = (int)((blockIdx.x * blockDim.x + threadIdx.x) >> 5);
    int lane = threadIdx.x & 31;
    if (gw >= nrows) return;
    int bt = gw / heads;
    int h  = gw - bt * heads;
    int t  = bt & (T_SEQ - 1);

    float* row = buf + (size_t)bt * heads * HD + (size_t)h * HD;

    float v[8];
    *(float4*)&v[0] = *(const float4*)(row + lane * 8);
    *(float4*)&v[4] = *(const float4*)(row + lane * 8 + 4);

    float ss = 0.f;
#pragma unroll
    for (int i = 0; i < 8; i++) ss += v[i] * v[i];
#pragma unroll
    for (int o = 16; o > 0; o >>= 1) ss += __shfl_xor_sync(0xffffffffu, ss, o);

    float r = rsqrtf(ss * (1.0f / HD) + 1e-6f);

    float g[8];
    *(float4*)&g[0] = *(const float4*)(gamma + lane * 8);
    *(float4*)&g[4] = *(const float4*)(gamma + lane * 8 + 4);

    float tf = (float)t;
#pragma unroll
    for (int p = 0; p < 4; p++) {
        int i   = lane * 4 + p;
        float e = (float)(2 * i) * (1.0f / HD);           // exactly representable
        float inv = (float)pow(1000000.0, -(double)e);    // fp64 -> correctly rounded fp32
        float ang = tf * inv;                             // fp32 product like jnp.outer
        float c, s;
        sincosf(ang, &s, &c);
        float x0 = v[2 * p]     * r * g[2 * p];
        float x1 = v[2 * p + 1] * r * g[2 * p + 1];
        v[2 * p]     = x0 * c - x1 * s;
        v[2 * p + 1] = x0 * s + x1 * c;
    }

    *(float4*)(row + lane * 8)     = *(float4*)&v[0];
    *(float4*)(row + lane * 8 + 4) = *(float4*)&v[4];
}

// ---------------- sliding-window attention (flash-style, fp32) -----------------
// CTA: 64 queries of one (b,h). Key tiles of 64; window=512 is tile-aligned so
// at most 9 tiles. Q,K transposed in smem ([d][j], pad 68) for conflict-free
// outer-product fragments; V natural [j][d]; P staged through smem.
__global__ __launch_bounds__(256, 1) void attn_swa(
    const float* __restrict__ Q, const float* __restrict__ Kb,
    const float* __restrict__ Vb, float* __restrict__ O)
{
    extern __shared__ float sm[];
    float* Qs = sm;                         // [256][PAD]
    float* Ks = Qs + 256 * PAD;             // [256][PAD]
    float* Vs = Ks + 256 * PAD;             // [64][256]
    float* Ps = Vs + 64 * HD;               // [64][PAD]

    const int tid = threadIdx.x;
    const int tx  = tid & 15;
    const int ty  = tid >> 4;
    const int qt  = blockIdx.x & 63;
    const int h   = (blockIdx.x >> 6) & 3;
    const int b   = blockIdx.x >> 8;
    const int q0  = qt << 6;

    const float* qbase = Q  + ((size_t)b * T_SEQ) * CDIM + (size_t)h * HD;
    const float* kbase = Kb + ((size_t)b * T_SEQ) * HD;
    const float* vbase = Vb + ((size_t)b * T_SEQ) * HD;

    // load Q tile transposed: Qs[d][j]
    {
        int j0 = tid >> 3;      // 0..31
        int d8 = tid & 7;       // 0..7
#pragma unroll
        for (int jj = 0; jj < 64; jj += 32)
#pragma unroll
            for (int dd = 0; dd < 8; dd++) {
                int d = (dd * 8 + d8) * 4;
                int j = jj + j0;
                float4 gq = *(const float4*)(qbase + (size_t)(q0 + j) * CDIM + d);
                Qs[(d + 0) * PAD + j] = gq.x;
                Qs[(d + 1) * PAD + j] = gq.y;
                Qs[(d + 2) * PAD + j] = gq.z;
                Qs[(d + 3) * PAD + j] = gq.w;
            }
    }

    float m_run[4], l_run[4], oacc[4][16];
#pragma unroll
    for (int qi = 0; qi < 4; qi++) {
        m_run[qi] = -1e30f; l_run[qi] = 0.f;
#pragma unroll
        for (int c = 0; c < 16; c++) oacc[qi][c] = 0.f;
    }

    int kt0 = q0 - WIN; if (kt0 < 0) kt0 = 0;

    for (int kt = kt0; kt <= q0; kt += 64) {
        __syncthreads();   // previous readers of Ks/Vs done (covers Qs on iter 0)

        // K tile transposed: Ks[d][j]
        {
            int j0 = tid >> 3, d8 = tid & 7;
#pragma unroll
            for (int jj = 0; jj < 64; jj += 32)
#pragma unroll
                for (int dd = 0; dd < 8; dd++) {
                    int d = (dd * 8 + d8) * 4;
                    int j = jj + j0;
                    float4 gk = *(const float4*)(kbase + (size_t)(kt + j) * HD + d);
                    Ks[(d + 0) * PAD + j] = gk.x;
                    Ks[(d + 1) * PAD + j] = gk.y;
                    Ks[(d + 2) * PAD + j] = gk.z;
                    Ks[(d + 3) * PAD + j] = gk.w;
                }
        }
        // V tile natural: Vs[j][d] (fully coalesced)
#pragma unroll
        for (int it = 0; it < 16; it++) {
            int idx = it * 256 + tid;
            int j = idx >> 6;
            int d = (idx & 63) * 4;
            *(float4*)(Vs + j * HD + d) =
                *(const float4*)(vbase + (size_t)(kt + j) * HD + d);
        }
        __syncthreads();

        // scores: S = Q·K^T, micro-tile 4q x 4k per thread
        float acc[4][4];
#pragma unroll
        for (int qi = 0; qi < 4; qi++)
#pragma unroll
            for (int ki = 0; ki < 4; ki++) acc[qi][ki] = 0.f;

#pragma unroll 8
        for (int d = 0; d < HD; d++) {
            float qa[4], ka[4];
            *(float4*)qa = *(const float4*)(Qs + d * PAD + ty * 4);
            *(float4*)ka = *(const float4*)(Ks + d * PAD + tx * 4);
#pragma unroll
            for (int qi = 0; qi < 4; qi++)
#pragma unroll
                for (int ki = 0; ki < 4; ki++)
                    acc[qi][ki] = fmaf(qa[qi], ka[ki], acc[qi][ki]);
        }

        // online softmax (rows = ty*4+qi, reduce over 16 tx lanes of half-warp)
#pragma unroll
        for (int qi = 0; qi < 4; qi++) {
            int irow = q0 + ty * 4 + qi;
            bool ok[4];
            float sv[4];
            float mt = -1e30f;
#pragma unroll
            for (int ki = 0; ki < 4; ki++) {
                int j = kt + tx * 4 + ki;
                ok[ki] = (j <= irow) && (j >= irow - WIN);
                sv[ki] = ok[ki] ? acc[qi][ki] * 0.0625f : -1e30f;
                mt = fmaxf(mt, sv[ki]);
            }
#pragma unroll
            for (int o = 1; o < 16; o <<= 1)
                mt = fmaxf(mt, __shfl_xor_sync(0xffffffffu, mt, o));
            float mnew = fmaxf(m_run[qi], mt);
            float corr = expf(m_run[qi] - mnew);
            float pv[4];
            float rs = 0.f;
#pragma unroll
            for (int ki = 0; ki < 4; ki++) {
                pv[ki] = ok[ki] ? expf(sv[ki] - mnew) : 0.f;
                rs += pv[ki];
            }
#pragma unroll
            for (int o = 1; o < 16; o <<= 1)
                rs += __shfl_xor_sync(0xffffffffu, rs, o);
            l_run[qi] = l_run[qi] * corr + rs;
            m_run[qi] = mnew;
#pragma unroll
            for (int c = 0; c < 16; c++) oacc[qi][c] *= corr;
            *(float4*)(Ps + (ty * 4 + qi) * PAD + tx * 4) =
                make_float4(pv[0], pv[1], pv[2], pv[3]);
        }
        __syncthreads();

        // O += P·V  (rows ty*4+qi; cols c*64 + tx*4 + u)
#pragma unroll 4
        for (int j = 0; j < 64; j++) {
            float pf[4];
#pragma unroll
            for (int qi = 0; qi < 4; qi++) pf[qi] = Ps[(ty * 4 + qi) * PAD + j];
#pragma unroll
            for (int c = 0; c < 4; c++) {
                float4 vf = *(const float4*)(Vs + j * HD + c * 64 + tx * 4);
#pragma unroll
                for (int qi = 0; qi < 4; qi++) {
                    oacc[qi][c * 4 + 0] = fmaf(pf[qi], vf.x, oacc[qi][c * 4 + 0]);
                    oacc[qi][c * 4 + 1] = fmaf(pf[qi], vf.y, oacc[qi][c * 4 + 1]);
                    oacc[qi][c * 4 + 2] = fmaf(pf[qi], vf.z, oacc[qi][c * 4 + 2]);
                    oacc[qi][c * 4 + 3] = fmaf(pf[qi], vf.w, oacc[qi][c * 4 + 3]);
                }
            }
        }
    }

    // epilogue: O /= l, write (B,T,H*hd)
#pragma unroll
    for (int qi = 0; qi < 4; qi++) {
        float inv = 1.f / l_run[qi];
        size_t row = (size_t)b * T_SEQ + q0 + ty * 4 + qi;
#pragma unroll
        for (int c = 0; c < 4; c++) {
            float4 o = make_float4(oacc[qi][c * 4 + 0] * inv, oacc[qi][c * 4 + 1] * inv,
                                   oacc[qi][c * 4 + 2] * inv, oacc[qi][c * 4 + 3] * inv);
            *(float4*)(O + row * CDIM + h * HD + c * 64 + tx * 4) = o;
        }
    }
}

// ---------------- launch ----------------
extern "C" void kernel_launch(void* const* d_in, const int* in_sizes, int n_in,
                              void* d_out, int out_size)
{
    const float* x  = (const float*)d_in[0];
    const float* Wq = (const float*)d_in[1];
    const float* Wk = (const float*)d_in[2];
    const float* Wv = (const float*)d_in[3];
    const float* Wo = (const float*)d_in[4];
    const float* qg = (const float*)d_in[5];
    const float* kg = (const float*)d_in[6];
    float* out = (float*)d_out;

    float *q, *k, *v, *ao;
    cudaGetSymbolAddress((void**)&q,  g_q);
    cudaGetSymbolAddress((void**)&k,  g_k);
    cudaGetSymbolAddress((void**)&v,  g_v);
    cudaGetSymbolAddress((void**)&ao, g_ao);

    const int M = BATCH * T_SEQ;   // 8192
    dim3 blk(256);

    // QKV projections
    sgemm_nt<<<dim3(CDIM / 128, M / 128), blk>>>(M, CDIM, CDIM, x, Wq, q);
    sgemm_nt<<<dim3(HD / 128,   M / 128), blk>>>(M, HD,   CDIM, x, Wk, k);
    sgemm_nt<<<dim3(HD / 128,   M / 128), blk>>>(M, HD,   CDIM, x, Wv, v);

    // RMSNorm + RoPE
    rmsnorm_rope<<<(M * NH) / 8, 256>>>(q, qg, M * NH, NH);
    rmsnorm_rope<<<M / 8, 256>>>(k, kg, M, 1);

    // sliding-window attention
    int smem = (2 * 256 * PAD + 64 * HD + 64 * PAD) * (int)sizeof(float); // 222208 B
    cudaFuncSetAttribute(attn_swa, cudaFuncAttributeMaxDynamicSharedMemorySize, smem);
    attn_swa<<<BATCH * NH * (T_SEQ / 64), 256, smem>>>(q, k, v, ao);

    // output projection
    sgemm_nt<<<dim3(CDIM / 128, M / 128), blk>>>(M, CDIM, CDIM, ao, Wo, out);
}

// round 2
// speedup vs baseline: 1.4028x; 1.4028x over previous
#include <cuda_runtime.h>
#include <math.h>
#include <stdint.h>

#define T_SEQ 4096
#define BATCH 2
#define CDIM  1024
#define HD    256
#define NH    4
#define WIN   512
#define PAD   68

// ---------------- scratch (static device globals; no allocation) ----------------
__device__ float g_q [(size_t)BATCH * T_SEQ * CDIM];   // 32 MB
__device__ float g_k [(size_t)BATCH * T_SEQ * HD];     // 8 MB
__device__ float g_v [(size_t)BATCH * T_SEQ * HD];     // 8 MB
__device__ float g_ao[(size_t)BATCH * T_SEQ * CDIM];   // 32 MB
__device__ float g_invf[HD / 2];                       // RoPE inverse frequencies

// ---------------- RoPE inv_freq table (one tiny launch; fp64 pow is free here) --
__global__ void init_invf()
{
    int i = threadIdx.x;                                // 0..127
    float e = (float)(2 * i) * (1.0f / HD);             // exactly representable
    g_invf[i] = (float)pow(1000000.0, -(double)e);      // correctly-rounded fp32
}

// ---------------- SGEMM: C[M,N] = A[M,K] * B[N,K]^T (all row-major) -------------
__global__ __launch_bounds__(256) void sgemm_nt(
    int M, int N, int K,
    const float* __restrict__ A,
    const float* __restrict__ B,
    float* __restrict__ C)
{
    __shared__ float As[8][128];
    __shared__ float Bs[8][128];

    const int tid = threadIdx.x;
    const int tx = tid & 15;
    const int ty = tid >> 4;
    const int m0 = blockIdx.y << 7;
    const int n0 = blockIdx.x << 7;
    const int lr = tid >> 1;
    const int lk = (tid & 1) << 2;

    const float* Ap = A + (size_t)(m0 + lr) * K + lk;
    const float* Bp = B + (size_t)(n0 + lr) * K + lk;

    float acc[8][8];
#pragma unroll
    for (int i = 0; i < 8; i++)
#pragma unroll
        for (int j = 0; j < 8; j++) acc[i][j] = 0.f;

    for (int k0 = 0; k0 < K; k0 += 8) {
        float4 a4 = *(const float4*)(Ap + k0);
        float4 b4 = *(const float4*)(Bp + k0);
        __syncthreads();
        As[lk + 0][lr] = a4.x; As[lk + 1][lr] = a4.y;
        As[lk + 2][lr] = a4.z; As[lk + 3][lr] = a4.w;
        Bs[lk + 0][lr] = b4.x; Bs[lk + 1][lr] = b4.y;
        Bs[lk + 2][lr] = b4.z; Bs[lk + 3][lr] = b4.w;
        __syncthreads();
#pragma unroll
        for (int kk = 0; kk < 8; kk++) {
            float a[8], b[8];
            *(float4*)&a[0] = *(const float4*)&As[kk][ty * 8];
            *(float4*)&a[4] = *(const float4*)&As[kk][ty * 8 + 4];
            *(float4*)&b[0] = *(const float4*)&Bs[kk][tx * 8];
            *(float4*)&b[4] = *(const float4*)&Bs[kk][tx * 8 + 4];
#pragma unroll
            for (int i = 0; i < 8; i++)
#pragma unroll
                for (int j = 0; j < 8; j++)
                    acc[i][j] = fmaf(a[i], b[j], acc[i][j]);
        }
    }

#pragma unroll
    for (int i = 0; i < 8; i++) {
        float* cp = C + (size_t)(m0 + ty * 8 + i) * N + n0 + tx * 8;
        float4 o0 = make_float4(acc[i][0], acc[i][1], acc[i][2], acc[i][3]);
        float4 o1 = make_float4(acc[i][4], acc[i][5], acc[i][6], acc[i][7]);
        *(float4*)cp       = o0;
        *(float4*)(cp + 4) = o1;
    }
}

// ---------------- fused RMSNorm + RoPE (1 warp per 256-wide head row) ----------
__global__ void rmsnorm_rope(float* __restrict__ buf, const float* __restrict__ gamma,
                             int nrows, int heads)
{
    int gw   = (int)((blockIdx.x * blockDim.x + threadIdx.x) >> 5);
    int lane = threadIdx.x & 31;
    if (gw >= nrows) return;
    int bt = gw / heads;
    int h  = gw - bt * heads;
    int t  = bt & (T_SEQ - 1);

    float* row = buf + (size_t)bt * heads * HD + (size_t)h * HD;

    float v[8];
    *(float4*)&v[0] = *(const float4*)(row + lane * 8);
    *(float4*)&v[4] = *(const float4*)(row + lane * 8 + 4);

    float ss = 0.f;
#pragma unroll
    for (int i = 0; i < 8; i++) ss += v[i] * v[i];
#pragma unroll
    for (int o = 16; o > 0; o >>= 1) ss += __shfl_xor_sync(0xffffffffu, ss, o);

    float r = rsqrtf(ss * (1.0f / HD) + 1e-6f);

    float g[8];
    *(float4*)&g[0] = *(const float4*)(gamma + lane * 8);
    *(float4*)&g[4] = *(const float4*)(gamma + lane * 8 + 4);

    float invf[4];
    *(float4*)invf = *(const float4*)(g_invf + lane * 4);

    float tf = (float)t;
#pragma unroll
    for (int p = 0; p < 4; p++) {
        float ang = tf * invf[p];          // fp32 product like jnp.outer
        float c, s;
        sincosf(ang, &s, &c);
        float x0 = v[2 * p]     * r * g[2 * p];
        float x1 = v[2 * p + 1] * r * g[2 * p + 1];
        v[2 * p]     = x0 * c - x1 * s;
        v[2 * p + 1] = x0 * s + x1 * c;
    }

    *(float4*)(row + lane * 8)     = *(float4*)&v[0];
    *(float4*)(row + lane * 8 + 4) = *(float4*)&v[4];
}

// ---------------- sliding-window attention (flash-style, fp32) -----------------
__global__ __launch_bounds__(256, 1) void attn_swa(
    const float* __restrict__ Q, const float* __restrict__ Kb,
    const float* __restrict__ Vb, float* __restrict__ O)
{
    extern __shared__ float sm[];
    float* Qs = sm;                         // [256][PAD]
    float* Ks = Qs + 256 * PAD;             // [256][PAD]
    float* Vs = Ks + 256 * PAD;             // [64][256]
    float* Ps = Vs + 64 * HD;               // [64][PAD]

    const int tid = threadIdx.x;
    const int tx  = tid & 15;
    const int ty  = tid >> 4;
    const int qt  = blockIdx.x & 63;
    const int h   = (blockIdx.x >> 6) & 3;
    const int b   = blockIdx.x >> 8;
    const int q0  = qt << 6;

    const float* qbase = Q  + ((size_t)b * T_SEQ) * CDIM + (size_t)h * HD;
    const float* kbase = Kb + ((size_t)b * T_SEQ) * HD;
    const float* vbase = Vb + ((size_t)b * T_SEQ) * HD;

    // load Q tile transposed: Qs[d][j]
    {
        int j0 = tid >> 3;      // 0..31
        int d8 = tid & 7;       // 0..7
#pragma unroll
        for (int jj = 0; jj < 64; jj += 32)
#pragma unroll
            for (int dd = 0; dd < 8; dd++) {
                int d = (dd * 8 + d8) * 4;
                int j = jj + j0;
                float4 gq = *(const float4*)(qbase + (size_t)(q0 + j) * CDIM + d);
                Qs[(d + 0) * PAD + j] = gq.x;
                Qs[(d + 1) * PAD + j] = gq.y;
                Qs[(d + 2) * PAD + j] = gq.z;
                Qs[(d + 3) * PAD + j] = gq.w;
            }
    }

    float m_run[4], l_run[4], oacc[4][16];
#pragma unroll
    for (int qi = 0; qi < 4; qi++) {
        m_run[qi] = -1e30f; l_run[qi] = 0.f;
#pragma unroll
        for (int c = 0; c < 16; c++) oacc[qi][c] = 0.f;
    }

    int kt0 = q0 - WIN; if (kt0 < 0) kt0 = 0;

    for (int kt = kt0; kt <= q0; kt += 64) {
        __syncthreads();   // previous readers of Ks/Vs done (covers Qs on iter 0)

        // K tile transposed: Ks[d][j]
        {
            int j0 = tid >> 3, d8 = tid & 7;
#pragma unroll
            for (int jj = 0; jj < 64; jj += 32)
#pragma unroll
                for (int dd = 0; dd < 8; dd++) {
                    int d = (dd * 8 + d8) * 4;
                    int j = jj + j0;
                    float4 gk = *(const float4*)(kbase + (size_t)(kt + j) * HD + d);
                    Ks[(d + 0) * PAD + j] = gk.x;
                    Ks[(d + 1) * PAD + j] = gk.y;
                    Ks[(d + 2) * PAD + j] = gk.z;
                    Ks[(d + 3) * PAD + j] = gk.w;
                }
        }
        // V tile natural: Vs[j][d] (fully coalesced)
#pragma unroll
        for (int it = 0; it < 16; it++) {
            int idx = it * 256 + tid;
            int j = idx >> 6;
            int d = (idx & 63) * 4;
            *(float4*)(Vs + j * HD + d) =
                *(const float4*)(vbase + (size_t)(kt + j) * HD + d);
        }
        __syncthreads();

        // scores: S = Q·K^T, micro-tile 4q x 4k per thread
        float acc[4][4];
#pragma unroll
        for (int qi = 0; qi < 4; qi++)
#pragma unroll
            for (int ki = 0; ki < 4; ki++) acc[qi][ki] = 0.f;

#pragma unroll 8
        for (int d = 0; d < HD; d++) {
            float qa[4], ka[4];
            *(float4*)qa = *(const float4*)(Qs + d * PAD + ty * 4);
            *(float4*)ka = *(const float4*)(Ks + d * PAD + tx * 4);
#pragma unroll
            for (int qi = 0; qi < 4; qi++)
#pragma unroll
                for (int ki = 0; ki < 4; ki++)
                    acc[qi][ki] = fmaf(qa[qi], ka[ki], acc[qi][ki]);
        }

        // online softmax (rows = ty*4+qi, reduce over 16 tx lanes of half-warp)
#pragma unroll
        for (int qi = 0; qi < 4; qi++) {
            int irow = q0 + ty * 4 + qi;
            bool ok[4];
            float sv[4];
            float mt = -1e30f;
#pragma unroll
            for (int ki = 0; ki < 4; ki++) {
                int j = kt + tx * 4 + ki;
                ok[ki] = (j <= irow) && (j >= irow - WIN);
                sv[ki] = ok[ki] ? acc[qi][ki] * 0.0625f : -1e30f;
                mt = fmaxf(mt, sv[ki]);
            }
#pragma unroll
            for (int o = 1; o < 16; o <<= 1)
                mt = fmaxf(mt, __shfl_xor_sync(0xffffffffu, mt, o));
            float mnew = fmaxf(m_run[qi], mt);
            float corr = __expf(m_run[qi] - mnew);
            float pv[4];
            float rs = 0.f;
#pragma unroll
            for (int ki = 0; ki < 4; ki++) {
                pv[ki] = ok[ki] ? __expf(sv[ki] - mnew) : 0.f;
                rs += pv[ki];
            }
#pragma unroll
            for (int o = 1; o < 16; o <<= 1)
                rs += __shfl_xor_sync(0xffffffffu, rs, o);
            l_run[qi] = l_run[qi] * corr + rs;
            m_run[qi] = mnew;
#pragma unroll
            for (int c = 0; c < 16; c++) oacc[qi][c] *= corr;
            *(float4*)(Ps + (ty * 4 + qi) * PAD + tx * 4) =
                make_float4(pv[0], pv[1], pv[2], pv[3]);
        }
        __syncthreads();

        // O += P·V  (rows ty*4+qi; cols c*64 + tx*4 + u)
#pragma unroll 4
        for (int j = 0; j < 64; j++) {
            float pf[4];
#pragma unroll
            for (int qi = 0; qi < 4; qi++) pf[qi] = Ps[(ty * 4 + qi) * PAD + j];
#pragma unroll
            for (int c = 0; c < 4; c++) {
                float4 vf = *(const float4*)(Vs + j * HD + c * 64 + tx * 4);
#pragma unroll
                for (int qi = 0; qi < 4; qi++) {
                    oacc[qi][c * 4 + 0] = fmaf(pf[qi], vf.x, oacc[qi][c * 4 + 0]);
                    oacc[qi][c * 4 + 1] = fmaf(pf[qi], vf.y, oacc[qi][c * 4 + 1]);
                    oacc[qi][c * 4 + 2] = fmaf(pf[qi], vf.z, oacc[qi][c * 4 + 2]);
                    oacc[qi][c * 4 + 3] = fmaf(pf[qi], vf.w, oacc[qi][c * 4 + 3]);
                }
            }
        }
    }

    // epilogue: O /= l, write (B,T,H*hd)
#pragma unroll
    for (int qi = 0; qi < 4; qi++) {
        float inv = 1.f / l_run[qi];
        size_t row = (size_t)b * T_SEQ + q0 + ty * 4 + qi;
#pragma unroll
        for (int c = 0; c < 4; c++) {
            float4 o = make_float4(oacc[qi][c * 4 + 0] * inv, oacc[qi][c * 4 + 1] * inv,
                                   oacc[qi][c * 4 + 2] * inv, oacc[qi][c * 4 + 3] * inv);
            *(float4*)(O + row * CDIM + h * HD + c * 64 + tx * 4) = o;
        }
    }
}

// ---------------- launch ----------------
extern "C" void kernel_launch(void* const* d_in, const int* in_sizes, int n_in,
                              void* d_out, int out_size)
{
    const float* x  = (const float*)d_in[0];
    const float* Wq = (const float*)d_in[1];
    const float* Wk = (const float*)d_in[2];
    const float* Wv = (const float*)d_in[3];
    const float* Wo = (const float*)d_in[4];
    const float* qg = (const float*)d_in[5];
    const float* kg = (const float*)d_in[6];
    float* out = (float*)d_out;

    float *q, *k, *v, *ao;
    cudaGetSymbolAddress((void**)&q,  g_q);
    cudaGetSymbolAddress((void**)&k,  g_k);
    cudaGetSymbolAddress((void**)&v,  g_v);
    cudaGetSymbolAddress((void**)&ao, g_ao);

    const int M = BATCH * T_SEQ;   // 8192
    dim3 blk(256);

    // RoPE tables (tiny, overlaps nothing of consequence)
    init_invf<<<1, 128>>>();

    // QKV projections
    sgemm_nt<<<dim3(CDIM / 128, M / 128), blk>>>(M, CDIM, CDIM, x, Wq, q);
    sgemm_nt<<<dim3(HD / 128,   M / 128), blk>>>(M, HD,   CDIM, x, Wk, k);
    sgemm_nt<<<dim3(HD / 128,   M / 128), blk>>>(M, HD,   CDIM, x, Wv, v);

    // RMSNorm + RoPE
    rmsnorm_rope<<<(M * NH) / 8, 256>>>(q, qg, M * NH, NH);
    rmsnorm_rope<<<M / 8, 256>>>(k, kg, M, 1);

    // sliding-window attention
    int smem = (2 * 256 * PAD + 64 * HD + 64 * PAD) * (int)sizeof(float); // 222208 B
    cudaFuncSetAttribute(attn_swa, cudaFuncAttributeMaxDynamicSharedMemorySize, smem);
    attn_swa<<<BATCH * NH * (T_SEQ / 64), 256, smem>>>(q, k, v, ao);

    // output projection
    sgemm_nt<<<dim3(CDIM / 128, M / 128), blk>>>(M, CDIM, CDIM, ao, Wo, out);
}

// round 4
// speedup vs baseline: 1.8105x; 1.2907x over previous
#include <cuda_runtime.h>
#include <math.h>
#include <stdint.h>

#define T_SEQ 4096
#define BATCH 2
#define CDIM  1024
#define HD    256
#define NH    4
#define WIN   512
#define PAD   68

// ---------------- scratch (static device globals; no allocation) ----------------
__device__ float g_q [(size_t)BATCH * T_SEQ * CDIM];
__device__ float g_k [(size_t)BATCH * T_SEQ * HD];
__device__ float g_v [(size_t)BATCH * T_SEQ * HD];
__device__ float g_ao[(size_t)BATCH * T_SEQ * CDIM];
__device__ float g_invf[HD / 2];

// ---------------- RoPE inv_freq table ----------------
__global__ void init_invf()
{
    int i = threadIdx.x;
    float e = (float)(2 * i) * (1.0f / HD);
    g_invf[i] = (float)pow(1000000.0, -(double)e);
}

// ================== split-TF32 mma.sync GEMM: C = A[M,K] * B[N,K]^T ==============
// CTA tile 128x128, BK=32, 8 warps (4 m x 2 n), warp tile 32x64.
// Legacy tensor path (HMMA) — valid in compute_103 PTX (no 'a' suffix needed).

#define BK 32
#define ASTRIDE 36                       // 32 + 4 pad floats (conflict-free frags)
#define TILE_BYTES (128 * ASTRIDE * 4)   // 18432
#define GEMM_SMEM (4 * TILE_BYTES)       // A0,B0,A1,B1 = 73728

__device__ __forceinline__ uint32_t smem_u32(const void* p) {
    uint32_t a;
    asm("{ .reg .u64 t; cvta.to.shared.u64 t, %1; cvt.u32.u64 %0, t; }" : "=r"(a) : "l"(p));
    return a;
}

__device__ __forceinline__ void split_tf32(float x, uint32_t& h, uint32_t& l) {
    asm("cvt.rna.tf32.f32 %0, %1;" : "=r"(h) : "f"(x));
    float r = x - __uint_as_float(h);
    asm("cvt.rna.tf32.f32 %0, %1;" : "=r"(l) : "f"(r));
}

#define MMA_TF32(d, a, b) \
    asm volatile("mma.sync.aligned.m16n8k8.row.col.f32.tf32.tf32.f32 " \
        "{%0,%1,%2,%3}, {%4,%5,%6,%7}, {%8,%9}, {%0,%1,%2,%3};" \
        : "+f"((d)[0]), "+f"((d)[1]), "+f"((d)[2]), "+f"((d)[3]) \
        : "r"((a)[0]), "r"((a)[1]), "r"((a)[2]), "r"((a)[3]), \
          "r"((b)[0]), "r"((b)[1]))

#define CP_ASYNC16(sa, ga) \
    asm volatile("cp.async.cg.shared.global [%0], [%1], 16;" :: "r"(sa), "l"(ga))
#define CP_COMMIT() asm volatile("cp.async.commit_group;" ::: "memory")
#define CP_WAIT0()  asm volatile("cp.async.wait_group 0;" ::: "memory")

__device__ __forceinline__ void gemm_gload(
    uint32_t sb, int buf, const float* __restrict__ A, const float* __restrict__ B,
    int m0, int n0, int kt, int K, int tid)
{
    uint32_t abase = sb + (uint32_t)buf * 2u * TILE_BYTES;
    uint32_t bbase = abase + TILE_BYTES;
#pragma unroll
    for (int i = 0; i < 4; i++) {
        int f   = i * 256 + tid;
        int row = f >> 3;
        int kc  = (f & 7) * 4;
        uint32_t so = (uint32_t)(row * ASTRIDE + kc) * 4u;
        CP_ASYNC16(abase + so, A + (size_t)(m0 + row) * K + kt + kc);
        CP_ASYNC16(bbase + so, B + (size_t)(n0 + row) * K + kt + kc);
    }
    CP_COMMIT();
}

__global__ __launch_bounds__(256, 2) void gemm_tf32_split(
    int M, int N, int K,
    const float* __restrict__ A, const float* __restrict__ B, float* __restrict__ C)
{
    extern __shared__ char smem[];
    const uint32_t sb = smem_u32(smem);
    const int tid    = threadIdx.x;
    const int wid    = tid >> 5;
    const int lane   = tid & 31;
    const int quad   = lane >> 2;
    const int tq     = lane & 3;
    const int warp_m = wid & 3;          // 0..3 -> 32 rows each
    const int warp_n = wid >> 2;         // 0..1 -> 64 cols each
    const int m0 = blockIdx.y << 7;
    const int n0 = blockIdx.x << 7;

    float acc[2][8][4];
#pragma unroll
    for (int mf = 0; mf < 2; mf++)
#pragma unroll
        for (int nf = 0; nf < 8; nf++)
#pragma unroll
            for (int r = 0; r < 4; r++) acc[mf][nf][r] = 0.f;

    const int NT = K / BK;

    gemm_gload(sb, 0, A, B, m0, n0, 0, K, tid);
    CP_WAIT0();
    __syncthreads();

    for (int it = 0; it < NT; ++it) {
        if (it + 1 < NT)
            gemm_gload(sb, (it + 1) & 1, A, B, m0, n0, (it + 1) * BK, K, tid);

        const float* As = (const float*)(smem + (size_t)(it & 1) * 2 * TILE_BYTES);
        const float* Bs = As + TILE_BYTES / 4;

#pragma unroll
        for (int ks = 0; ks < 4; ks++) {
            const int k0 = ks * 8;
            uint32_t ah[2][4], al[2][4];
#pragma unroll
            for (int mf = 0; mf < 2; mf++) {
                int r = warp_m * 32 + mf * 16 + quad;
                split_tf32(As[(r    ) * ASTRIDE + k0 + tq    ], ah[mf][0], al[mf][0]);
                split_tf32(As[(r + 8) * ASTRIDE + k0 + tq    ], ah[mf][1], al[mf][1]);
                split_tf32(As[(r    ) * ASTRIDE + k0 + tq + 4], ah[mf][2], al[mf][2]);
                split_tf32(As[(r + 8) * ASTRIDE + k0 + tq + 4], ah[mf][3], al[mf][3]);
            }
#pragma unroll
            for (int nf = 0; nf < 8; nf++) {
                int c = warp_n * 64 + nf * 8 + quad;
                uint32_t bh[2], bl[2];
                split_tf32(Bs[c * ASTRIDE + k0 + tq    ], bh[0], bl[0]);
                split_tf32(Bs[c * ASTRIDE + k0 + tq + 4], bh[1], bl[1]);
#pragma unroll
                for (int mf = 0; mf < 2; mf++) {
                    MMA_TF32(acc[mf][nf], ah[mf], bh);
                    MMA_TF32(acc[mf][nf], ah[mf], bl);
                    MMA_TF32(acc[mf][nf], al[mf], bh);
                }
            }
        }

        if (it + 1 < NT) CP_WAIT0();
        __syncthreads();
    }

    // epilogue: C rows = m0 + warp_m*32 + mf*16 + quad (+8); cols per C-frag layout
#pragma unroll
    for (int mf = 0; mf < 2; mf++) {
        int row = m0 + warp_m * 32 + mf * 16 + quad;
#pragma unroll
        for (int nf = 0; nf < 8; nf++) {
            int col = n0 + warp_n * 64 + nf * 8 + tq * 2;
            *(float2*)(C + (size_t)row * N + col)       = make_float2(acc[mf][nf][0], acc[mf][nf][1]);
            *(float2*)(C + (size_t)(row + 8) * N + col) = make_float2(acc[mf][nf][2], acc[mf][nf][3]);
        }
    }
}

// ---------------- fused RMSNorm + RoPE ----------------
__global__ void rmsnorm_rope(float* __restrict__ buf, const float* __restrict__ gamma,
                             int nrows, int heads)
{
    int gw   = (int)((blockIdx.x * blockDim.x + threadIdx.x) >> 5);
    int lane = threadIdx.x & 31;
    if (gw >= nrows) return;
    int bt = gw / heads;
    int h  = gw - bt * heads;
    int t  = bt & (T_SEQ - 1);

    float* row = buf + (size_t)bt * heads * HD + (size_t)h * HD;

    float v[8];
    *(float4*)&v[0] = *(const float4*)(row + lane * 8);
    *(float4*)&v[4] = *(const float4*)(row + lane * 8 + 4);

    float ss = 0.f;
#pragma unroll
    for (int i = 0; i < 8; i++) ss += v[i] * v[i];
#pragma unroll
    for (int o = 16; o > 0; o >>= 1) ss += __shfl_xor_sync(0xffffffffu, ss, o);

    float r = rsqrtf(ss * (1.0f / HD) + 1e-6f);

    float g[8];
    *(float4*)&g[0] = *(const float4*)(gamma + lane * 8);
    *(float4*)&g[4] = *(const float4*)(gamma + lane * 8 + 4);

    float invf[4];
    *(float4*)invf = *(const float4*)(g_invf + lane * 4);

    float tf = (float)t;
#pragma unroll
    for (int p = 0; p < 4; p++) {
        float ang = tf * invf[p];
        float c, s;
        sincosf(ang, &s, &c);
        float x0 = v[2 * p]     * r * g[2 * p];
        float x1 = v[2 * p + 1] * r * g[2 * p + 1];
        v[2 * p]     = x0 * c - x1 * s;
        v[2 * p + 1] = x0 * s + x1 * c;
    }

    *(float4*)(row + lane * 8)     = *(float4*)&v[0];
    *(float4*)(row + lane * 8 + 4) = *(float4*)&v[4];
}

// ---------------- sliding-window attention (flash-style, fp32) -----------------
__global__ __launch_bounds__(256, 1) void attn_swa(
    const float* __restrict__ Q, const float* __restrict__ Kb,
    const float* __restrict__ Vb, float* __restrict__ O)
{
    extern __shared__ float sm[];
    float* Qs = sm;                         // [256][PAD]
    float* Ks = Qs + 256 * PAD;             // [256][PAD]
    float* Vs = Ks + 256 * PAD;             // [64][256]
    float* Ps = Vs + 64 * HD;               // [64][PAD]

    const int tid = threadIdx.x;
    const int tx  = tid & 15;
    const int ty  = tid >> 4;
    const int qt  = blockIdx.x & 63;
    const int h   = (blockIdx.x >> 6) & 3;
    const int b   = blockIdx.x >> 8;
    const int q0  = qt << 6;

    const float* qbase = Q  + ((size_t)b * T_SEQ) * CDIM + (size_t)h * HD;
    const float* kbase = Kb + ((size_t)b * T_SEQ) * HD;
    const float* vbase = Vb + ((size_t)b * T_SEQ) * HD;

    {
        int j0 = tid >> 3;
        int d8 = tid & 7;
#pragma unroll
        for (int jj = 0; jj < 64; jj += 32)
#pragma unroll
            for (int dd = 0; dd < 8; dd++) {
                int d = (dd * 8 + d8) * 4;
                int j = jj + j0;
                float4 gq = *(const float4*)(qbase + (size_t)(q0 + j) * CDIM + d);
                Qs[(d + 0) * PAD + j] = gq.x;
                Qs[(d + 1) * PAD + j] = gq.y;
                Qs[(d + 2) * PAD + j] = gq.z;
                Qs[(d + 3) * PAD + j] = gq.w;
            }
    }

    float m_run[4], l_run[4], oacc[4][16];
#pragma unroll
    for (int qi = 0; qi < 4; qi++) {
        m_run[qi] = -1e30f; l_run[qi] = 0.f;
#pragma unroll
        for (int c = 0; c < 16; c++) oacc[qi][c] = 0.f;
    }

    int kt0 = q0 - WIN; if (kt0 < 0) kt0 = 0;

    for (int kt = kt0; kt <= q0; kt += 64) {
        __syncthreads();

        {
            int j0 = tid >> 3, d8 = tid & 7;
#pragma unroll
            for (int jj = 0; jj < 64; jj += 32)
#pragma unroll
                for (int dd = 0; dd < 8; dd++) {
                    int d = (dd * 8 + d8) * 4;
                    int j = jj + j0;
                    float4 gk = *(const float4*)(kbase + (size_t)(kt + j) * HD + d);
                    Ks[(d + 0) * PAD + j] = gk.x;
                    Ks[(d + 1) * PAD + j] = gk.y;
                    Ks[(d + 2) * PAD + j] = gk.z;
                    Ks[(d + 3) * PAD + j] = gk.w;
                }
        }
#pragma unroll
        for (int it = 0; it < 16; it++) {
            int idx = it * 256 + tid;
            int j = idx >> 6;
            int d = (idx & 63) * 4;
            *(float4*)(Vs + j * HD + d) =
                *(const float4*)(vbase + (size_t)(kt + j) * HD + d);
        }
        __syncthreads();

        float acc[4][4];
#pragma unroll
        for (int qi = 0; qi < 4; qi++)
#pragma unroll
            for (int ki = 0; ki < 4; ki++) acc[qi][ki] = 0.f;

#pragma unroll 8
        for (int d = 0; d < HD; d++) {
            float qa[4], ka[4];
            *(float4*)qa = *(const float4*)(Qs + d * PAD + ty * 4);
            *(float4*)ka = *(const float4*)(Ks + d * PAD + tx * 4);
#pragma unroll
            for (int qi = 0; qi < 4; qi++)
#pragma unroll
                for (int ki = 0; ki < 4; ki++)
                    acc[qi][ki] = fmaf(qa[qi], ka[ki], acc[qi][ki]);
        }

#pragma unroll
        for (int qi = 0; qi < 4; qi++) {
            int irow = q0 + ty * 4 + qi;
            bool ok[4];
            float sv[4];
            float mt = -1e30f;
#pragma unroll
            for (int ki = 0; ki < 4; ki++) {
                int j = kt + tx * 4 + ki;
                ok[ki] = (j <= irow) && (j >= irow - WIN);
                sv[ki] = ok[ki] ? acc[qi][ki] * 0.0625f : -1e30f;
                mt = fmaxf(mt, sv[ki]);
            }
#pragma unroll
            for (int o = 1; o < 16; o <<= 1)
                mt = fmaxf(mt, __shfl_xor_sync(0xffffffffu, mt, o));
            float mnew = fmaxf(m_run[qi], mt);
            float corr = __expf(m_run[qi] - mnew);
            float pv[4];
            float rs = 0.f;
#pragma unroll
            for (int ki = 0; ki < 4; ki++) {
                pv[ki] = ok[ki] ? __expf(sv[ki] - mnew) : 0.f;
                rs += pv[ki];
            }
#pragma unroll
            for (int o = 1; o < 16; o <<= 1)
                rs += __shfl_xor_sync(0xffffffffu, rs, o);
            l_run[qi] = l_run[qi] * corr + rs;
            m_run[qi] = mnew;
#pragma unroll
            for (int c = 0; c < 16; c++) oacc[qi][c] *= corr;
            *(float4*)(Ps + (ty * 4 + qi) * PAD + tx * 4) =
                make_float4(pv[0], pv[1], pv[2], pv[3]);
        }
        __syncthreads();

#pragma unroll 4
        for (int j = 0; j < 64; j++) {
            float pf[4];
#pragma unroll
            for (int qi = 0; qi < 4; qi++) pf[qi] = Ps[(ty * 4 + qi) * PAD + j];
#pragma unroll
            for (int c = 0; c < 4; c++) {
                float4 vf = *(const float4*)(Vs + j * HD + c * 64 + tx * 4);
#pragma unroll
                for (int qi = 0; qi < 4; qi++) {
                    oacc[qi][c * 4 + 0] = fmaf(pf[qi], vf.x, oacc[qi][c * 4 + 0]);
                    oacc[qi][c * 4 + 1] = fmaf(pf[qi], vf.y, oacc[qi][c * 4 + 1]);
                    oacc[qi][c * 4 + 2] = fmaf(pf[qi], vf.z, oacc[qi][c * 4 + 2]);
                    oacc[qi][c * 4 + 3] = fmaf(pf[qi], vf.w, oacc[qi][c * 4 + 3]);
                }
            }
        }
    }

#pragma unroll
    for (int qi = 0; qi < 4; qi++) {
        float inv = 1.f / l_run[qi];
        size_t row = (size_t)b * T_SEQ + q0 + ty * 4 + qi;
#pragma unroll
        for (int c = 0; c < 4; c++) {
            float4 o = make_float4(oacc[qi][c * 4 + 0] * inv, oacc[qi][c * 4 + 1] * inv,
                                   oacc[qi][c * 4 + 2] * inv, oacc[qi][c * 4 + 3] * inv);
            *(float4*)(O + row * CDIM + h * HD + c * 64 + tx * 4) = o;
        }
    }
}

// ---------------- launch ----------------
extern "C" void kernel_launch(void* const* d_in, const int* in_sizes, int n_in,
                              void* d_out, int out_size)
{
    const float* x  = (const float*)d_in[0];
    const float* Wq = (const float*)d_in[1];
    const float* Wk = (const float*)d_in[2];
    const float* Wv = (const float*)d_in[3];
    const float* Wo = (const float*)d_in[4];
    const float* qg = (const float*)d_in[5];
    const float* kg = (const float*)d_in[6];
    float* out = (float*)d_out;

    float *q, *k, *v, *ao;
    cudaGetSymbolAddress((void**)&q,  g_q);
    cudaGetSymbolAddress((void**)&k,  g_k);
    cudaGetSymbolAddress((void**)&v,  g_v);
    cudaGetSymbolAddress((void**)&ao, g_ao);

    const int M = BATCH * T_SEQ;   // 8192

    init_invf<<<1, 128>>>();

    cudaFuncSetAttribute(gemm_tf32_split, cudaFuncAttributeMaxDynamicSharedMemorySize, GEMM_SMEM);

    // QKV projections (split-tf32 tensor-core mma.sync)
    gemm_tf32_split<<<dim3(CDIM / 128, M / 128), 256, GEMM_SMEM>>>(M, CDIM, CDIM, x, Wq, q);
    gemm_tf32_split<<<dim3(HD / 128,   M / 128), 256, GEMM_SMEM>>>(M, HD,   CDIM, x, Wk, k);
    gemm_tf32_split<<<dim3(HD / 128,   M / 128), 256, GEMM_SMEM>>>(M, HD,   CDIM, x, Wv, v);

    // RMSNorm + RoPE
    rmsnorm_rope<<<(M * NH) / 8, 256>>>(q, qg, M * NH, NH);
    rmsnorm_rope<<<M / 8, 256>>>(k, kg, M, 1);

    // sliding-window attention
    int smem = (2 * 256 * PAD + 64 * HD + 64 * PAD) * (int)sizeof(float);
    cudaFuncSetAttribute(attn_swa, cudaFuncAttributeMaxDynamicSharedMemorySize, smem);
    attn_swa<<<BATCH * NH * (T_SEQ / 64), 256, smem>>>(q, k, v, ao);

    // output projection
    gemm_tf32_split<<<dim3(CDIM / 128, M / 128), 256, GEMM_SMEM>>>(M, CDIM, CDIM, ao, Wo, out);
}

// round 5
// speedup vs baseline: 2.3498x; 1.2979x over previous
#include <cuda_runtime.h>
#include <math.h>
#include <stdint.h>

#define T_SEQ 4096
#define BATCH 2
#define CDIM  1024
#define HD    256
#define NH    4
#define WIN   512
#define PAD   68

// ---------------- scratch (static device globals; no allocation) ----------------
__device__ float g_q [(size_t)BATCH * T_SEQ * CDIM];
__device__ float g_k [(size_t)BATCH * T_SEQ * HD];
__device__ float g_v [(size_t)BATCH * T_SEQ * HD];
__device__ float g_ao[(size_t)BATCH * T_SEQ * CDIM];
__device__ float g_invf[HD / 2];

// ---------------- RoPE inv_freq table ----------------
__global__ void init_invf()
{
    int i = threadIdx.x;
    float e = (float)(2 * i) * (1.0f / HD);
    g_invf[i] = (float)pow(1000000.0, -(double)e);
}

// ============ split-BF16 mma.sync GEMM: C = A[M,K] * B[N,K]^T ============
// CTA tile 128x128, BK=32, 8 warps (4m x 2n), warp tile 32x64.
// fp32 = hi(bf16) + lo(bf16); 3 bf16 MMAs (hh, hl, lh) per k16-step.
// Split ONCE in the loader; smem holds packed bf16x2 hi/lo tiles.

#define BK 32
#define STR 18                              // uint32 per row (16 pairs + 2 pad)
#define TILE_U32 (128 * STR)                // 2304
#define GEMM_SMEM (2 * 4 * TILE_U32 * 4)    // 2 buf x {Ah,Al,Bh,Bl} = 73728 B

__device__ __forceinline__ void split_bf16(float x, uint16_t& h, uint16_t& l) {
    asm("cvt.rn.bf16.f32 %0, %1;" : "=h"(h) : "f"(x));
    float r = x - __uint_as_float((uint32_t)h << 16);   // exact
    asm("cvt.rn.bf16.f32 %0, %1;" : "=h"(l) : "f"(r));
}

#define MMA_BF16(d, a, b) \
    asm volatile("mma.sync.aligned.m16n8k16.row.col.f32.bf16.bf16.f32 " \
        "{%0,%1,%2,%3}, {%4,%5,%6,%7}, {%8,%9}, {%0,%1,%2,%3};" \
        : "+f"((d)[0]), "+f"((d)[1]), "+f"((d)[2]), "+f"((d)[3]) \
        : "r"((a)[0]), "r"((a)[1]), "r"((a)[2]), "r"((a)[3]), \
          "r"((b)[0]), "r"((b)[1]))

__global__ __launch_bounds__(256, 2) void gemm_bf16_split(
    int M, int N, int K,
    const float* __restrict__ A,
    const float* __restrict__ B0, const float* __restrict__ B1,
    float* __restrict__ C0, float* __restrict__ C1)
{
    extern __shared__ uint32_t s32[];
    const float* B = blockIdx.z ? B1 : B0;
    float*       C = blockIdx.z ? C1 : C0;

    const int tid    = threadIdx.x;
    const int wid    = tid >> 5;
    const int lane   = tid & 31;
    const int quad   = lane >> 2;
    const int tq     = lane & 3;
    const int warp_m = wid & 3;
    const int warp_n = wid >> 2;
    const int m0 = blockIdx.y << 7;
    const int n0 = blockIdx.x << 7;

    // per-thread load map: 4 chunks, each = one float4 of A and of B
    int f_row[4], f_pb[4];
#pragma unroll
    for (int i = 0; i < 4; i++) {
        int f = i * 256 + tid;
        f_row[i] = f >> 3;
        f_pb[i]  = (f & 7) * 2;     // pair index of first of 2 uint32
    }

    float acc[2][8][4];
#pragma unroll
    for (int mf = 0; mf < 2; mf++)
#pragma unroll
        for (int nf = 0; nf < 8; nf++)
#pragma unroll
            for (int r = 0; r < 4; r++) acc[mf][nf][r] = 0.f;

    const int NT = K / BK;
    float4 avr[4], bvr[4];

    // --- load chunk kt into registers ---
#define LOADG(kt) do { \
    _Pragma("unroll") \
    for (int i = 0; i < 4; i++) { \
        int kc = f_pb[i] * 2; \
        avr[i] = *(const float4*)(A + (size_t)(m0 + f_row[i]) * K + (kt) + kc); \
        bvr[i] = *(const float4*)(B + (size_t)(n0 + f_row[i]) * K + (kt) + kc); \
    } } while (0)

    // --- split + store registers to smem buffer ---
#define STORES(buf) do { \
    uint32_t* Ah = s32 + (buf) * 4 * TILE_U32; \
    uint32_t* Al = Ah + TILE_U32; \
    uint32_t* Bh = Al + TILE_U32; \
    uint32_t* Bl = Bh + TILE_U32; \
    _Pragma("unroll") \
    for (int i = 0; i < 4; i++) { \
        uint16_t h0,h1,h2,h3,l0,l1,l2,l3; \
        int o = f_row[i] * STR + f_pb[i]; \
        split_bf16(avr[i].x,h0,l0); split_bf16(avr[i].y,h1,l1); \
        split_bf16(avr[i].z,h2,l2); split_bf16(avr[i].w,h3,l3); \
        Ah[o]   = (uint32_t)h0 | ((uint32_t)h1 << 16); \
        Ah[o+1] = (uint32_t)h2 | ((uint32_t)h3 << 16); \
        Al[o]   = (uint32_t)l0 | ((uint32_t)l1 << 16); \
        Al[o+1] = (uint32_t)l2 | ((uint32_t)l3 << 16); \
        split_bf16(bvr[i].x,h0,l0); split_bf16(bvr[i].y,h1,l1); \
        split_bf16(bvr[i].z,h2,l2); split_bf16(bvr[i].w,h3,l3); \
        Bh[o]   = (uint32_t)h0 | ((uint32_t)h1 << 16); \
        Bh[o+1] = (uint32_t)h2 | ((uint32_t)h3 << 16); \
        Bl[o]   = (uint32_t)l0 | ((uint32_t)l1 << 16); \
        Bl[o+1] = (uint32_t)l2 | ((uint32_t)l3 << 16); \
    } } while (0)

    LOADG(0);
    STORES(0);
    __syncthreads();

    for (int it = 0; it < NT; ++it) {
        if (it + 1 < NT) LOADG((it + 1) * BK);

        const uint32_t* Ah = s32 + (it & 1) * 4 * TILE_U32;
        const uint32_t* Al = Ah + TILE_U32;
        const uint32_t* Bh = Al + TILE_U32;
        const uint32_t* Bl = Bh + TILE_U32;

#pragma unroll
        for (int ks = 0; ks < 2; ks++) {
            const int kb = ks * 8;
            uint32_t ah[2][4], al[2][4];
#pragma unroll
            for (int mf = 0; mf < 2; mf++) {
                int r = warp_m * 32 + mf * 16 + quad;
                ah[mf][0] = Ah[(r    ) * STR + kb + tq];
                ah[mf][1] = Ah[(r + 8) * STR + kb + tq];
                ah[mf][2] = Ah[(r    ) * STR + kb + tq + 4];
                ah[mf][3] = Ah[(r + 8) * STR + kb + tq + 4];
                al[mf][0] = Al[(r    ) * STR + kb + tq];
                al[mf][1] = Al[(r + 8) * STR + kb + tq];
                al[mf][2] = Al[(r    ) * STR + kb + tq + 4];
                al[mf][3] = Al[(r + 8) * STR + kb + tq + 4];
            }
#pragma unroll
            for (int nf = 0; nf < 8; nf++) {
                int c = warp_n * 64 + nf * 8 + quad;
                uint32_t bh[2], bl[2];
                bh[0] = Bh[c * STR + kb + tq];
                bh[1] = Bh[c * STR + kb + tq + 4];
                bl[0] = Bl[c * STR + kb + tq];
                bl[1] = Bl[c * STR + kb + tq + 4];
#pragma unroll
                for (int mf = 0; mf < 2; mf++) {
                    MMA_BF16(acc[mf][nf], ah[mf], bh);
                    MMA_BF16(acc[mf][nf], ah[mf], bl);
                    MMA_BF16(acc[mf][nf], al[mf], bh);
                }
            }
        }

        if (it + 1 < NT) STORES((it + 1) & 1);
        __syncthreads();
    }

    // epilogue
#pragma unroll
    for (int mf = 0; mf < 2; mf++) {
        int row = m0 + warp_m * 32 + mf * 16 + quad;
#pragma unroll
        for (int nf = 0; nf < 8; nf++) {
            int col = n0 + warp_n * 64 + nf * 8 + tq * 2;
            *(float2*)(C + (size_t)row * N + col)       = make_float2(acc[mf][nf][0], acc[mf][nf][1]);
            *(float2*)(C + (size_t)(row + 8) * N + col) = make_float2(acc[mf][nf][2], acc[mf][nf][3]);
        }
    }
#undef LOADG
#undef STORES
}

// ---------------- fused RMSNorm + RoPE ----------------
__global__ void rmsnorm_rope(float* __restrict__ buf, const float* __restrict__ gamma,
                             int nrows, int heads)
{
    int gw   = (int)((blockIdx.x * blockDim.x + threadIdx.x) >> 5);
    int lane = threadIdx.x & 31;
    if (gw >= nrows) return;
    int bt = gw / heads;
    int h  = gw - bt * heads;
    int t  = bt & (T_SEQ - 1);

    float* row = buf + (size_t)bt * heads * HD + (size_t)h * HD;

    float v[8];
    *(float4*)&v[0] = *(const float4*)(row + lane * 8);
    *(float4*)&v[4] = *(const float4*)(row + lane * 8 + 4);

    float ss = 0.f;
#pragma unroll
    for (int i = 0; i < 8; i++) ss += v[i] * v[i];
#pragma unroll
    for (int o = 16; o > 0; o >>= 1) ss += __shfl_xor_sync(0xffffffffu, ss, o);

    float r = rsqrtf(ss * (1.0f / HD) + 1e-6f);

    float g[8];
    *(float4*)&g[0] = *(const float4*)(gamma + lane * 8);
    *(float4*)&g[4] = *(const float4*)(gamma + lane * 8 + 4);

    float invf[4];
    *(float4*)invf = *(const float4*)(g_invf + lane * 4);

    float tf = (float)t;
#pragma unroll
    for (int p = 0; p < 4; p++) {
        float ang = tf * invf[p];
        float c, s;
        sincosf(ang, &s, &c);
        float x0 = v[2 * p]     * r * g[2 * p];
        float x1 = v[2 * p + 1] * r * g[2 * p + 1];
        v[2 * p]     = x0 * c - x1 * s;
        v[2 * p + 1] = x0 * s + x1 * c;
    }

    *(float4*)(row + lane * 8)     = *(float4*)&v[0];
    *(float4*)(row + lane * 8 + 4) = *(float4*)&v[4];
}

// ---------------- sliding-window attention (flash-style, fp32) -----------------
__global__ __launch_bounds__(256, 1) void attn_swa(
    const float* __restrict__ Q, const float* __restrict__ Kb,
    const float* __restrict__ Vb, float* __restrict__ O)
{
    extern __shared__ float sm[];
    float* Qs = sm;                         // [256][PAD]
    float* Ks = Qs + 256 * PAD;             // [256][PAD]
    float* Vs = Ks + 256 * PAD;             // [64][256]
    float* Ps = Vs + 64 * HD;               // [64][PAD]

    const int tid = threadIdx.x;
    const int tx  = tid & 15;
    const int ty  = tid >> 4;
    const int qt  = blockIdx.x & 63;
    const int h   = (blockIdx.x >> 6) & 3;
    const int b   = blockIdx.x >> 8;
    const int q0  = qt << 6;

    const float* qbase = Q  + ((size_t)b * T_SEQ) * CDIM + (size_t)h * HD;
    const float* kbase = Kb + ((size_t)b * T_SEQ) * HD;
    const float* vbase = Vb + ((size_t)b * T_SEQ) * HD;

    {
        int j0 = tid >> 3;
        int d8 = tid & 7;
#pragma unroll
        for (int jj = 0; jj < 64; jj += 32)
#pragma unroll
            for (int dd = 0; dd < 8; dd++) {
                int d = (dd * 8 + d8) * 4;
                int j = jj + j0;
                float4 gq = *(const float4*)(qbase + (size_t)(q0 + j) * CDIM + d);
                Qs[(d + 0) * PAD + j] = gq.x;
                Qs[(d + 1) * PAD + j] = gq.y;
                Qs[(d + 2) * PAD + j] = gq.z;
                Qs[(d + 3) * PAD + j] = gq.w;
            }
    }

    float m_run[4], l_run[4], oacc[4][16];
#pragma unroll
    for (int qi = 0; qi < 4; qi++) {
        m_run[qi] = -1e30f; l_run[qi] = 0.f;
#pragma unroll
        for (int c = 0; c < 16; c++) oacc[qi][c] = 0.f;
    }

    int kt0 = q0 - WIN; if (kt0 < 0) kt0 = 0;

    for (int kt = kt0; kt <= q0; kt += 64) {
        __syncthreads();

        {
            int j0 = tid >> 3, d8 = tid & 7;
#pragma unroll
            for (int jj = 0; jj < 64; jj += 32)
#pragma unroll
                for (int dd = 0; dd < 8; dd++) {
                    int d = (dd * 8 + d8) * 4;
                    int j = jj + j0;
                    float4 gk = *(const float4*)(kbase + (size_t)(kt + j) * HD + d);
                    Ks[(d + 0) * PAD + j] = gk.x;
                    Ks[(d + 1) * PAD + j] = gk.y;
                    Ks[(d + 2) * PAD + j] = gk.z;
                    Ks[(d + 3) * PAD + j] = gk.w;
                }
        }
#pragma unroll
        for (int it = 0; it < 16; it++) {
            int idx = it * 256 + tid;
            int j = idx >> 6;
            int d = (idx & 63) * 4;
            *(float4*)(Vs + j * HD + d) =
                *(const float4*)(vbase + (size_t)(kt + j) * HD + d);
        }
        __syncthreads();

        float acc[4][4];
#pragma unroll
        for (int qi = 0; qi < 4; qi++)
#pragma unroll
            for (int ki = 0; ki < 4; ki++) acc[qi][ki] = 0.f;

#pragma unroll 8
        for (int d = 0; d < HD; d++) {
            float qa[4], ka[4];
            *(float4*)qa = *(const float4*)(Qs + d * PAD + ty * 4);
            *(float4*)ka = *(const float4*)(Ks + d * PAD + tx * 4);
#pragma unroll
            for (int qi = 0; qi < 4; qi++)
#pragma unroll
                for (int ki = 0; ki < 4; ki++)
                    acc[qi][ki] = fmaf(qa[qi], ka[ki], acc[qi][ki]);
        }

#pragma unroll
        for (int qi = 0; qi < 4; qi++) {
            int irow = q0 + ty * 4 + qi;
            bool ok[4];
            float sv[4];
            float mt = -1e30f;
#pragma unroll
            for (int ki = 0; ki < 4; ki++) {
                int j = kt + tx * 4 + ki;
                ok[ki] = (j <= irow) && (j >= irow - WIN);
                sv[ki] = ok[ki] ? acc[qi][ki] * 0.0625f : -1e30f;
                mt = fmaxf(mt, sv[ki]);
            }
#pragma unroll
            for (int o = 1; o < 16; o <<= 1)
                mt = fmaxf(mt, __shfl_xor_sync(0xffffffffu, mt, o));
            float mnew = fmaxf(m_run[qi], mt);
            float corr = __expf(m_run[qi] - mnew);
            float pv[4];
            float rs = 0.f;
#pragma unroll
            for (int ki = 0; ki < 4; ki++) {
                pv[ki] = ok[ki] ? __expf(sv[ki] - mnew) : 0.f;
                rs += pv[ki];
            }
#pragma unroll
            for (int o = 1; o < 16; o <<= 1)
                rs += __shfl_xor_sync(0xffffffffu, rs, o);
            l_run[qi] = l_run[qi] * corr + rs;
            m_run[qi] = mnew;
#pragma unroll
            for (int c = 0; c < 16; c++) oacc[qi][c] *= corr;
            *(float4*)(Ps + (ty * 4 + qi) * PAD + tx * 4) =
                make_float4(pv[0], pv[1], pv[2], pv[3]);
        }
        __syncthreads();

#pragma unroll 4
        for (int j = 0; j < 64; j++) {
            float pf[4];
#pragma unroll
            for (int qi = 0; qi < 4; qi++) pf[qi] = Ps[(ty * 4 + qi) * PAD + j];
#pragma unroll
            for (int c = 0; c < 4; c++) {
                float4 vf = *(const float4*)(Vs + j * HD + c * 64 + tx * 4);
#pragma unroll
                for (int qi = 0; qi < 4; qi++) {
                    oacc[qi][c * 4 + 0] = fmaf(pf[qi], vf.x, oacc[qi][c * 4 + 0]);
                    oacc[qi][c * 4 + 1] = fmaf(pf[qi], vf.y, oacc[qi][c * 4 + 1]);
                    oacc[qi][c * 4 + 2] = fmaf(pf[qi], vf.z, oacc[qi][c * 4 + 2]);
                    oacc[qi][c * 4 + 3] = fmaf(pf[qi], vf.w, oacc[qi][c * 4 + 3]);
                }
            }
        }
    }

#pragma unroll
    for (int qi = 0; qi < 4; qi++) {
        float inv = 1.f / l_run[qi];
        size_t row = (size_t)b * T_SEQ + q0 + ty * 4 + qi;
#pragma unroll
        for (int c = 0; c < 4; c++) {
            float4 o = make_float4(oacc[qi][c * 4 + 0] * inv, oacc[qi][c * 4 + 1] * inv,
                                   oacc[qi][c * 4 + 2] * inv, oacc[qi][c * 4 + 3] * inv);
            *(float4*)(O + row * CDIM + h * HD + c * 64 + tx * 4) = o;
        }
    }
}

// ---------------- launch ----------------
extern "C" void kernel_launch(void* const* d_in, const int* in_sizes, int n_in,
                              void* d_out, int out_size)
{
    const float* x  = (const float*)d_in[0];
    const float* Wq = (const float*)d_in[1];
    const float* Wk = (const float*)d_in[2];
    const float* Wv = (const float*)d_in[3];
    const float* Wo = (const float*)d_in[4];
    const float* qg = (const float*)d_in[5];
    const float* kg = (const float*)d_in[6];
    float* out = (float*)d_out;

    float *q, *k, *v, *ao;
    cudaGetSymbolAddress((void**)&q,  g_q);
    cudaGetSymbolAddress((void**)&k,  g_k);
    cudaGetSymbolAddress((void**)&v,  g_v);
    cudaGetSymbolAddress((void**)&ao, g_ao);

    const int M = BATCH * T_SEQ;   // 8192

    init_invf<<<1, 128>>>();

    cudaFuncSetAttribute(gemm_bf16_split, cudaFuncAttributeMaxDynamicSharedMemorySize, GEMM_SMEM);

    // Q projection
    gemm_bf16_split<<<dim3(CDIM / 128, M / 128, 1), 256, GEMM_SMEM>>>(
        M, CDIM, CDIM, x, Wq, Wq, q, q);
    // K and V projections fused in one launch (z selects weight/output)
    gemm_bf16_split<<<dim3(HD / 128, M / 128, 2), 256, GEMM_SMEM>>>(
        M, HD, CDIM, x, Wk, Wv, k, v);

    // RMSNorm + RoPE
    rmsnorm_rope<<<(M * NH) / 8, 256>>>(q, qg, M * NH, NH);
    rmsnorm_rope<<<M / 8, 256>>>(k, kg, M, 1);

    // sliding-window attention
    int smem = (2 * 256 * PAD + 64 * HD + 64 * PAD) * (int)sizeof(float);
    cudaFuncSetAttribute(attn_swa, cudaFuncAttributeMaxDynamicSharedMemorySize, smem);
    attn_swa<<<BATCH * NH * (T_SEQ / 64), 256, smem>>>(q, k, v, ao);

    // output projection
    gemm_bf16_split<<<dim3(CDIM / 128, M / 128, 1), 256, GEMM_SMEM>>>(
        M, CDIM, CDIM, ao, Wo, Wo, out, out);
}

// round 6
// speedup vs baseline: 2.9698x; 1.2639x over previous
#include <cuda_runtime.h>
#include <math.h>
#include <stdint.h>

#define T_SEQ 4096
#define BATCH 2
#define CDIM  1024
#define HD    256
#define NH    4
#define WIN   512

// ---------------- scratch (static device globals; no allocation) ----------------
__device__ float g_q [(size_t)BATCH * T_SEQ * CDIM];
__device__ float g_k [(size_t)BATCH * T_SEQ * HD];
__device__ float g_v [(size_t)BATCH * T_SEQ * HD];
__device__ float g_ao[(size_t)BATCH * T_SEQ * CDIM];
__device__ float g_invf[HD / 2];

// ---------------- RoPE inv_freq table ----------------
__global__ void init_invf()
{
    int i = threadIdx.x;
    float e = (float)(2 * i) * (1.0f / HD);
    g_invf[i] = (float)pow(1000000.0, -(double)e);
}

// ---------------- common bf16-split helpers ----------------
__device__ __forceinline__ void split_bf16(float x, uint16_t& h, uint16_t& l) {
    asm("cvt.rn.bf16.f32 %0, %1;" : "=h"(h) : "f"(x));
    float r = x - __uint_as_float((uint32_t)h << 16);   // exact
    asm("cvt.rn.bf16.f32 %0, %1;" : "=h"(l) : "f"(r));
}
__device__ __forceinline__ uint32_t pack2(uint16_t a, uint16_t b) {
    return (uint32_t)a | ((uint32_t)b << 16);
}

#define MMA_BF16(d, a, b) \
    asm volatile("mma.sync.aligned.m16n8k16.row.col.f32.bf16.bf16.f32 " \
        "{%0,%1,%2,%3}, {%4,%5,%6,%7}, {%8,%9}, {%0,%1,%2,%3};" \
        : "+f"((d)[0]), "+f"((d)[1]), "+f"((d)[2]), "+f"((d)[3]) \
        : "r"((a)[0]), "r"((a)[1]), "r"((a)[2]), "r"((a)[3]), \
          "r"((b)[0]), "r"((b)[1]))

// ============ split-BF16 mma.sync GEMM: C = A[M,K] * B[N,K]^T ============
#define BK 32
#define STR 18
#define TILE_U32 (128 * STR)
#define GEMM_SMEM (2 * 4 * TILE_U32 * 4)

__global__ __launch_bounds__(256, 2) void gemm_bf16_split(
    int M, int N, int K,
    const float* __restrict__ A,
    const float* __restrict__ B0, const float* __restrict__ B1,
    float* __restrict__ C0, float* __restrict__ C1)
{
    extern __shared__ uint32_t s32[];
    const float* B = blockIdx.z ? B1 : B0;
    float*       C = blockIdx.z ? C1 : C0;

    const int tid    = threadIdx.x;
    const int wid    = tid >> 5;
    const int lane   = tid & 31;
    const int quad   = lane >> 2;
    const int tq     = lane & 3;
    const int warp_m = wid & 3;
    const int warp_n = wid >> 2;
    const int m0 = blockIdx.y << 7;
    const int n0 = blockIdx.x << 7;

    int f_row[4], f_pb[4];
#pragma unroll
    for (int i = 0; i < 4; i++) {
        int f = i * 256 + tid;
        f_row[i] = f >> 3;
        f_pb[i]  = (f & 7) * 2;
    }

    float acc[2][8][4];
#pragma unroll
    for (int mf = 0; mf < 2; mf++)
#pragma unroll
        for (int nf = 0; nf < 8; nf++)
#pragma unroll
            for (int r = 0; r < 4; r++) acc[mf][nf][r] = 0.f;

    const int NT = K / BK;
    float4 avr[4], bvr[4];

#define LOADG(kt) do { \
    _Pragma("unroll") \
    for (int i = 0; i < 4; i++) { \
        int kc = f_pb[i] * 2; \
        avr[i] = *(const float4*)(A + (size_t)(m0 + f_row[i]) * K + (kt) + kc); \
        bvr[i] = *(const float4*)(B + (size_t)(n0 + f_row[i]) * K + (kt) + kc); \
    } } while (0)

#define STORES(buf) do { \
    uint32_t* Ah = s32 + (buf) * 4 * TILE_U32; \
    uint32_t* Al = Ah + TILE_U32; \
    uint32_t* Bh = Al + TILE_U32; \
    uint32_t* Bl = Bh + TILE_U32; \
    _Pragma("unroll") \
    for (int i = 0; i < 4; i++) { \
        uint16_t h0,h1,h2,h3,l0,l1,l2,l3; \
        int o = f_row[i] * STR + f_pb[i]; \
        split_bf16(avr[i].x,h0,l0); split_bf16(avr[i].y,h1,l1); \
        split_bf16(avr[i].z,h2,l2); split_bf16(avr[i].w,h3,l3); \
        Ah[o]   = pack2(h0,h1); Ah[o+1] = pack2(h2,h3); \
        Al[o]   = pack2(l0,l1); Al[o+1] = pack2(l2,l3); \
        split_bf16(bvr[i].x,h0,l0); split_bf16(bvr[i].y,h1,l1); \
        split_bf16(bvr[i].z,h2,l2); split_bf16(bvr[i].w,h3,l3); \
        Bh[o]   = pack2(h0,h1); Bh[o+1] = pack2(h2,h3); \
        Bl[o]   = pack2(l0,l1); Bl[o+1] = pack2(l2,l3); \
    } } while (0)

    LOADG(0);
    STORES(0);
    __syncthreads();

    for (int it = 0; it < NT; ++it) {
        if (it + 1 < NT) LOADG((it + 1) * BK);

        const uint32_t* Ah = s32 + (it & 1) * 4 * TILE_U32;
        const uint32_t* Al = Ah + TILE_U32;
        const uint32_t* Bh = Al + TILE_U32;
        const uint32_t* Bl = Bh + TILE_U32;

#pragma unroll
        for (int ks = 0; ks < 2; ks++) {
            const int kb = ks * 8;
            uint32_t ah[2][4], al[2][4];
#pragma unroll
            for (int mf = 0; mf < 2; mf++) {
                int r = warp_m * 32 + mf * 16 + quad;
                ah[mf][0] = Ah[(r    ) * STR + kb + tq];
                ah[mf][1] = Ah[(r + 8) * STR + kb + tq];
                ah[mf][2] = Ah[(r    ) * STR + kb + tq + 4];
                ah[mf][3] = Ah[(r + 8) * STR + kb + tq + 4];
                al[mf][0] = Al[(r    ) * STR + kb + tq];
                al[mf][1] = Al[(r + 8) * STR + kb + tq];
                al[mf][2] = Al[(r    ) * STR + kb + tq + 4];
                al[mf][3] = Al[(r + 8) * STR + kb + tq + 4];
            }
#pragma unroll
            for (int nf = 0; nf < 8; nf++) {
                int c = warp_n * 64 + nf * 8 + quad;
                uint32_t bh[2], bl[2];
                bh[0] = Bh[c * STR + kb + tq];
                bh[1] = Bh[c * STR + kb + tq + 4];
                bl[0] = Bl[c * STR + kb + tq];
                bl[1] = Bl[c * STR + kb + tq + 4];
#pragma unroll
                for (int mf = 0; mf < 2; mf++) {
                    MMA_BF16(acc[mf][nf], ah[mf], bh);
                    MMA_BF16(acc[mf][nf], ah[mf], bl);
                    MMA_BF16(acc[mf][nf], al[mf], bh);
                }
            }
        }

        if (it + 1 < NT) STORES((it + 1) & 1);
        __syncthreads();
    }

#pragma unroll
    for (int mf = 0; mf < 2; mf++) {
        int row = m0 + warp_m * 32 + mf * 16 + quad;
#pragma unroll
        for (int nf = 0; nf < 8; nf++) {
            int col = n0 + warp_n * 64 + nf * 8 + tq * 2;
            *(float2*)(C + (size_t)row * N + col)       = make_float2(acc[mf][nf][0], acc[mf][nf][1]);
            *(float2*)(C + (size_t)(row + 8) * N + col) = make_float2(acc[mf][nf][2], acc[mf][nf][3]);
        }
    }
#undef LOADG
#undef STORES
}

// ---------------- fused RMSNorm + RoPE ----------------
__global__ void rmsnorm_rope(float* __restrict__ buf, const float* __restrict__ gamma,
                             int nrows, int heads)
{
    int gw   = (int)((blockIdx.x * blockDim.x + threadIdx.x) >> 5);
    int lane = threadIdx.x & 31;
    if (gw >= nrows) return;
    int bt = gw / heads;
    int h  = gw - bt * heads;
    int t  = bt & (T_SEQ - 1);

    float* row = buf + (size_t)bt * heads * HD + (size_t)h * HD;

    float v[8];
    *(float4*)&v[0] = *(const float4*)(row + lane * 8);
    *(float4*)&v[4] = *(const float4*)(row + lane * 8 + 4);

    float ss = 0.f;
#pragma unroll
    for (int i = 0; i < 8; i++) ss += v[i] * v[i];
#pragma unroll
    for (int o = 16; o > 0; o >>= 1) ss += __shfl_xor_sync(0xffffffffu, ss, o);

    float r = rsqrtf(ss * (1.0f / HD) + 1e-6f);

    float g[8];
    *(float4*)&g[0] = *(const float4*)(gamma + lane * 8);
    *(float4*)&g[4] = *(const float4*)(gamma + lane * 8 + 4);

    float invf[4];
    *(float4*)invf = *(const float4*)(g_invf + lane * 4);

    float tf = (float)t;
#pragma unroll
    for (int p = 0; p < 4; p++) {
        float ang = tf * invf[p];
        float c, s;
        sincosf(ang, &s, &c);
        float x0 = v[2 * p]     * r * g[2 * p];
        float x1 = v[2 * p + 1] * r * g[2 * p + 1];
        v[2 * p]     = x0 * c - x1 * s;
        v[2 * p + 1] = x0 * s + x1 * c;
    }

    *(float4*)(row + lane * 8)     = *(float4*)&v[0];
    *(float4*)(row + lane * 8 + 4) = *(float4*)&v[4];
}

// =========== sliding-window flash attention, split-bf16 mma.sync ===========
// CTA: 64 queries of one (b,h); key tiles of 64. 8 warps (2m x 4n).
// smem (u32 offsets):
//   Qh[64][132], Ql            : Q split, pairs along d
//   KVh[9216], KVl             : union: K split [64][132]  OR  V split [256][36]
//   Ph[64][36], Pl             : P split, pairs along key
//   Vst fp32 [32][261]         : V staging for transpose
//   red[4][64], m_s/l_s/corr_s[64]
#define AQ_STR 132
#define AV_STR 36
#define VS_STR 261
#define ATTN_SMEM_U32 (2*64*AQ_STR + 2*9216 + 2*64*AV_STR)
#define ATTN_SMEM (ATTN_SMEM_U32*4 + 32*VS_STR*4 + (256+192)*4)   // 194944 B

__global__ __launch_bounds__(256, 1) void attn_swa_mma(
    const float* __restrict__ Q, const float* __restrict__ Kg,
    const float* __restrict__ Vg, float* __restrict__ O)
{
    extern __shared__ uint32_t s[];
    uint32_t* Qh  = s;
    uint32_t* Ql  = Qh + 64 * AQ_STR;
    uint32_t* KVh = Ql + 64 * AQ_STR;
    uint32_t* KVl = KVh + 9216;
    uint32_t* Ph  = KVl + 9216;
    uint32_t* Pl  = Ph + 64 * AV_STR;
    float* Vst    = (float*)(Pl + 64 * AV_STR);
    float* red    = Vst + 32 * VS_STR;
    float* m_s    = red + 256;
    float* l_s    = m_s + 64;
    float* corr_s = l_s + 64;

    const int tid  = threadIdx.x;
    const int wid  = tid >> 5, lane = tid & 31, quad = lane >> 2, tq = lane & 3;
    const int wm   = wid & 1, wn = wid >> 1;          // 2m x 4n warp grid
    const int qt   = blockIdx.x & 63;
    const int h    = (blockIdx.x >> 6) & 3;
    const int b    = blockIdx.x >> 8;
    const int q0   = qt << 6;

    const float* qbase = Q  + ((size_t)(b * T_SEQ + q0)) * CDIM + (size_t)h * HD;
    const float* kbase = Kg + (size_t)b * T_SEQ * HD;
    const float* vbase = Vg + (size_t)b * T_SEQ * HD;

    // ---- load + split Q tile (once) ----
#pragma unroll
    for (int i = 0; i < 16; i++) {
        int f = i * 256 + tid, row = f >> 6, c4 = f & 63;
        float4 v4 = *(const float4*)(qbase + (size_t)row * CDIM + c4 * 4);
        uint16_t h0,h1,h2,h3,l0,l1,l2,l3;
        split_bf16(v4.x,h0,l0); split_bf16(v4.y,h1,l1);
        split_bf16(v4.z,h2,l2); split_bf16(v4.w,h3,l3);
        int o = row * AQ_STR + c4 * 2;
        Qh[o] = pack2(h0,h1); Qh[o+1] = pack2(h2,h3);
        Ql[o] = pack2(l0,l1); Ql[o+1] = pack2(l2,l3);
    }
    if (tid < 64) { m_s[tid] = -1e30f; l_s[tid] = 0.f; }

    float oacc[2][8][4];
#pragma unroll
    for (int mf = 0; mf < 2; mf++)
#pragma unroll
        for (int nf = 0; nf < 8; nf++)
#pragma unroll
            for (int r = 0; r < 4; r++) oacc[mf][nf][r] = 0.f;

    int kt0 = q0 - WIN; if (kt0 < 0) kt0 = 0;

    for (int kt = kt0; kt <= q0; kt += 64) {
        __syncthreads();   // A: prev PV done reading KVh(V)/Ph; Q/m_s visible on iter 0

        // ---- load + split K tile ----
#pragma unroll
        for (int i = 0; i < 16; i++) {
            int f = i * 256 + tid, row = f >> 6, c4 = f & 63;
            float4 v4 = *(const float4*)(kbase + (size_t)(kt + row) * HD + c4 * 4);
            uint16_t h0,h1,h2,h3,l0,l1,l2,l3;
            split_bf16(v4.x,h0,l0); split_bf16(v4.y,h1,l1);
            split_bf16(v4.z,h2,l2); split_bf16(v4.w,h3,l3);
            int o = row * AQ_STR + c4 * 2;
            KVh[o] = pack2(h0,h1); KVh[o+1] = pack2(h2,h3);
            KVl[o] = pack2(l0,l1); KVl[o+1] = pack2(l2,l3);
        }
        __syncthreads();   // B

        // ---- S = Q K^T (split: hh + hl + lh) ----
        float sacc[2][2][4];
#pragma unroll
        for (int mf = 0; mf < 2; mf++)
#pragma unroll
            for (int nf = 0; nf < 2; nf++)
#pragma unroll
                for (int r = 0; r < 4; r++) sacc[mf][nf][r] = 0.f;

#pragma unroll
        for (int ks = 0; ks < 16; ks++) {
            const int kb = ks * 8;
            uint32_t ah[2][4], al[2][4];
#pragma unroll
            for (int mf = 0; mf < 2; mf++) {
                int r = wm * 32 + mf * 16 + quad;
                ah[mf][0] = Qh[(r    ) * AQ_STR + kb + tq];
                ah[mf][1] = Qh[(r + 8) * AQ_STR + kb + tq];
                ah[mf][2] = Qh[(r    ) * AQ_STR + kb + tq + 4];
                ah[mf][3] = Qh[(r + 8) * AQ_STR + kb + tq + 4];
                al[mf][0] = Ql[(r    ) * AQ_STR + kb + tq];
                al[mf][1] = Ql[(r + 8) * AQ_STR + kb + tq];
                al[mf][2] = Ql[(r    ) * AQ_STR + kb + tq + 4];
                al[mf][3] = Ql[(r + 8) * AQ_STR + kb + tq + 4];
            }
#pragma unroll
            for (int nf = 0; nf < 2; nf++) {
                int c = wn * 16 + nf * 8 + quad;
                uint32_t bh[2], bl[2];
                bh[0] = KVh[c * AQ_STR + kb + tq];
                bh[1] = KVh[c * AQ_STR + kb + tq + 4];
                bl[0] = KVl[c * AQ_STR + kb + tq];
                bl[1] = KVl[c * AQ_STR + kb + tq + 4];
#pragma unroll
                for (int mf = 0; mf < 2; mf++) {
                    MMA_BF16(sacc[mf][nf], ah[mf], bh);
                    MMA_BF16(sacc[mf][nf], ah[mf], bl);
                    MMA_BF16(sacc[mf][nf], al[mf], bh);
                }
            }
        }

        // ---- mask + scale + row max (fragments) ----
#pragma unroll
        for (int mf = 0; mf < 2; mf++)
#pragma unroll
            for (int half = 0; half < 2; half++) {
                int rowl = wm * 32 + mf * 16 + quad + half * 8;
                int irow = q0 + rowl;
                float mt = -1e30f;
#pragma unroll
                for (int nf = 0; nf < 2; nf++)
#pragma unroll
                    for (int p = 0; p < 2; p++) {
                        int j = kt + wn * 16 + nf * 8 + tq * 2 + p;
                        bool ok = (j <= irow) && (j >= irow - WIN);
                        float x = ok ? sacc[mf][nf][half * 2 + p] * 0.0625f : -1e30f;
                        sacc[mf][nf][half * 2 + p] = x;
                        mt = fmaxf(mt, x);
                    }
                mt = fmaxf(mt, __shfl_xor_sync(0xffffffffu, mt, 1));
                mt = fmaxf(mt, __shfl_xor_sync(0xffffffffu, mt, 2));
                if (tq == 0) red[wn * 64 + rowl] = mt;
            }
        __syncthreads();   // C

        if (wid < 2 && tq == 0) {
#pragma unroll
            for (int mf = 0; mf < 2; mf++)
#pragma unroll
                for (int half = 0; half < 2; half++) {
                    int rowl = wid * 32 + mf * 16 + quad + half * 8;
                    float mt = fmaxf(fmaxf(red[rowl], red[64 + rowl]),
                                     fmaxf(red[128 + rowl], red[192 + rowl]));
                    float mo = m_s[rowl];
                    float mn = fmaxf(mo, mt);
                    corr_s[rowl] = __expf(mo - mn);
                    m_s[rowl]    = mn;
                }
        }
        __syncthreads();   // D

        // ---- P = exp(S - m); split -> Ph/Pl; row sums ----
#pragma unroll
        for (int mf = 0; mf < 2; mf++)
#pragma unroll
            for (int half = 0; half < 2; half++) {
                int rowl = wm * 32 + mf * 16 + quad + half * 8;
                float mn = m_s[rowl];
                float rs = 0.f;
#pragma unroll
                for (int nf = 0; nf < 2; nf++) {
                    float p0 = __expf(sacc[mf][nf][half * 2 + 0] - mn);
                    float p1 = __expf(sacc[mf][nf][half * 2 + 1] - mn);
                    rs += p0 + p1;
                    uint16_t h0, l0, h1, l1;
                    split_bf16(p0, h0, l0); split_bf16(p1, h1, l1);
                    int o = rowl * AV_STR + wn * 8 + nf * 4 + tq;
                    Ph[o] = pack2(h0, h1);
                    Pl[o] = pack2(l0, l1);
                }
                rs += __shfl_xor_sync(0xffffffffu, rs, 1);
                rs += __shfl_xor_sync(0xffffffffu, rs, 2);
                if (tq == 0) red[wn * 64 + rowl] = rs;
            }
        __syncthreads();   // E

        if (wid < 2 && tq == 0) {
#pragma unroll
            for (int mf = 0; mf < 2; mf++)
#pragma unroll
                for (int half = 0; half < 2; half++) {
                    int rowl = wid * 32 + mf * 16 + quad + half * 8;
                    l_s[rowl] = l_s[rowl] * corr_s[rowl] +
                                red[rowl] + red[64 + rowl] + red[128 + rowl] + red[192 + rowl];
                }
        }
        // rescale PV accumulators
#pragma unroll
        for (int mf = 0; mf < 2; mf++) {
            int r0 = wm * 32 + mf * 16 + quad;
            float c0 = corr_s[r0], c1 = corr_s[r0 + 8];
#pragma unroll
            for (int nf = 0; nf < 8; nf++) {
                oacc[mf][nf][0] *= c0; oacc[mf][nf][1] *= c0;
                oacc[mf][nf][2] *= c1; oacc[mf][nf][3] *= c1;
            }
        }

        // ---- V: stage + transpose-split, two 32-key halves into KVh/KVl ----
#pragma unroll
        for (int hf = 0; hf < 2; hf++) {
            __syncthreads();   // F/H: Vstage free
#pragma unroll
            for (int i = 0; i < 8; i++) {
                int f = i * 256 + tid, row = f >> 6, c4 = f & 63;
                float4 v4 = *(const float4*)(vbase + (size_t)(kt + hf * 32 + row) * HD + c4 * 4);
                float* dst = Vst + row * VS_STR + c4 * 4;
                dst[0] = v4.x; dst[1] = v4.y; dst[2] = v4.z; dst[3] = v4.w;
            }
            __syncthreads();   // G/I
            {
                int j  = lane;
                int d0 = wid * 32;
                int key = hf * 32 + j;
                uint16_t* KVh16 = (uint16_t*)KVh;
                uint16_t* KVl16 = (uint16_t*)KVl;
#pragma unroll
                for (int i = 0; i < 32; i++) {
                    int d = d0 + i;
                    float x = Vst[j * VS_STR + d];
                    uint16_t hh, ll;
                    split_bf16(x, hh, ll);
                    int word = d * AV_STR + (key >> 1);
                    KVh16[word * 2 + (key & 1)] = hh;
                    KVl16[word * 2 + (key & 1)] = ll;
                }
            }
        }
        __syncthreads();   // J

        // ---- O += P V (split) ----
#pragma unroll
        for (int kk = 0; kk < 4; kk++) {
            const int kb = kk * 8;
            uint32_t pah[2][4], pal[2][4];
#pragma unroll
            for (int mf = 0; mf < 2; mf++) {
                int r = wm * 32 + mf * 16 + quad;
                pah[mf][0] = Ph[(r    ) * AV_STR + kb + tq];
                pah[mf][1] = Ph[(r + 8) * AV_STR + kb + tq];
                pah[mf][2] = Ph[(r    ) * AV_STR + kb + tq + 4];
                pah[mf][3] = Ph[(r + 8) * AV_STR + kb + tq + 4];
                pal[mf][0] = Pl[(r    ) * AV_STR + kb + tq];
                pal[mf][1] = Pl[(r + 8) * AV_STR + kb + tq];
                pal[mf][2] = Pl[(r    ) * AV_STR + kb + tq + 4];
                pal[mf][3] = Pl[(r + 8) * AV_STR + kb + tq + 4];
            }
#pragma unroll
            for (int nf = 0; nf < 8; nf++) {
                int c = wn * 64 + nf * 8 + quad;
                uint32_t vbh[2], vbl[2];
                vbh[0] = KVh[c * AV_STR + kb + tq];
                vbh[1] = KVh[c * AV_STR + kb + tq + 4];
                vbl[0] = KVl[c * AV_STR + kb + tq];
                vbl[1] = KVl[c * AV_STR + kb + tq + 4];
#pragma unroll
                for (int mf = 0; mf < 2; mf++) {
                    MMA_BF16(oacc[mf][nf], pah[mf], vbh);
                    MMA_BF16(oacc[mf][nf], pah[mf], vbl);
                    MMA_BF16(oacc[mf][nf], pal[mf], vbh);
                }
            }
        }
    }

    // ---- epilogue ----
#pragma unroll
    for (int mf = 0; mf < 2; mf++) {
        int r0 = wm * 32 + mf * 16 + quad;
        float i0 = 1.f / l_s[r0], i1 = 1.f / l_s[r0 + 8];
        float* ob = O + ((size_t)(b * T_SEQ + q0 + r0)) * CDIM + (size_t)h * HD;
#pragma unroll
        for (int nf = 0; nf < 8; nf++) {
            int col = wn * 64 + nf * 8 + tq * 2;
            *(float2*)(ob + col)            = make_float2(oacc[mf][nf][0] * i0, oacc[mf][nf][1] * i0);
            *(float2*)(ob + 8 * CDIM + col) = make_float2(oacc[mf][nf][2] * i1, oacc[mf][nf][3] * i1);
        }
    }
}

// ---------------- launch ----------------
extern "C" void kernel_launch(void* const* d_in, const int* in_sizes, int n_in,
                              void* d_out, int out_size)
{
    const float* x  = (const float*)d_in[0];
    const float* Wq = (const float*)d_in[1];
    const float* Wk = (const float*)d_in[2];
    const float* Wv = (const float*)d_in[3];
    const float* Wo = (const float*)d_in[4];
    const float* qg = (const float*)d_in[5];
    const float* kg = (const float*)d_in[6];
    float* out = (float*)d_out;

    float *q, *k, *v, *ao;
    cudaGetSymbolAddress((void**)&q,  g_q);
    cudaGetSymbolAddress((void**)&k,  g_k);
    cudaGetSymbolAddress((void**)&v,  g_v);
    cudaGetSymbolAddress((void**)&ao, g_ao);

    const int M = BATCH * T_SEQ;   // 8192

    init_invf<<<1, 128>>>();

    cudaFuncSetAttribute(gemm_bf16_split, cudaFuncAttributeMaxDynamicSharedMemorySize, GEMM_SMEM);

    gemm_bf16_split<<<dim3(CDIM / 128, M / 128, 1), 256, GEMM_SMEM>>>(
        M, CDIM, CDIM, x, Wq, Wq, q, q);
    gemm_bf16_split<<<dim3(HD / 128, M / 128, 2), 256, GEMM_SMEM>>>(
        M, HD, CDIM, x, Wk, Wv, k, v);

    rmsnorm_rope<<<(M * NH) / 8, 256>>>(q, qg, M * NH, NH);
    rmsnorm_rope<<<M / 8, 256>>>(k, kg, M, 1);

    cudaFuncSetAttribute(attn_swa_mma, cudaFuncAttributeMaxDynamicSharedMemorySize, ATTN_SMEM);
    attn_swa_mma<<<BATCH * NH * (T_SEQ / 64), 256, ATTN_SMEM>>>(q, k, v, ao);

    gemm_bf16_split<<<dim3(CDIM / 128, M / 128, 1), 256, GEMM_SMEM>>>(
        M, CDIM, CDIM, ao, Wo, Wo, out, out);
}

// round 7
// speedup vs baseline: 3.2075x; 1.0800x over previous
#include <cuda_runtime.h>
#include <math.h>
#include <stdint.h>

#define T_SEQ 4096
#define BATCH 2
#define CDIM  1024
#define HD    256
#define NH    4
#define WIN   512

// ---------------- scratch (static device globals; no allocation) ----------------
__device__ float    g_q [(size_t)BATCH * T_SEQ * CDIM];
__device__ float    g_k [(size_t)BATCH * T_SEQ * HD];
__device__ float    g_v [(size_t)BATCH * T_SEQ * HD];
__device__ float    g_invf[HD / 2];
// packed bf16x2 hi/lo operand buffers
__device__ uint32_t g_xh [(size_t)BATCH * T_SEQ * CDIM / 2];
__device__ uint32_t g_xl [(size_t)BATCH * T_SEQ * CDIM / 2];
__device__ uint32_t g_aoh[(size_t)BATCH * T_SEQ * CDIM / 2];
__device__ uint32_t g_aol[(size_t)BATCH * T_SEQ * CDIM / 2];
__device__ uint32_t g_wqh[CDIM * CDIM / 2];
__device__ uint32_t g_wql[CDIM * CDIM / 2];
__device__ uint32_t g_wkh[HD * CDIM / 2];
__device__ uint32_t g_wkl[HD * CDIM / 2];
__device__ uint32_t g_wvh[HD * CDIM / 2];
__device__ uint32_t g_wvl[HD * CDIM / 2];
__device__ uint32_t g_woh[CDIM * CDIM / 2];
__device__ uint32_t g_wol[CDIM * CDIM / 2];

// ---------------- RoPE inv_freq table ----------------
__global__ void init_invf()
{
    int i = threadIdx.x;
    float e = (float)(2 * i) * (1.0f / HD);
    g_invf[i] = (float)pow(1000000.0, -(double)e);
}

// ---------------- common bf16-split helpers ----------------
__device__ __forceinline__ void split_bf16(float x, uint16_t& h, uint16_t& l) {
    asm("cvt.rn.bf16.f32 %0, %1;" : "=h"(h) : "f"(x));
    float r = x - __uint_as_float((uint32_t)h << 16);   // exact
    asm("cvt.rn.bf16.f32 %0, %1;" : "=h"(l) : "f"(r));
}
__device__ __forceinline__ uint32_t pack2(uint16_t a, uint16_t b) {
    return (uint32_t)a | ((uint32_t)b << 16);
}

#define MMA_BF16(d, a, b) \
    asm volatile("mma.sync.aligned.m16n8k16.row.col.f32.bf16.bf16.f32 " \
        "{%0,%1,%2,%3}, {%4,%5,%6,%7}, {%8,%9}, {%0,%1,%2,%3};" \
        : "+f"((d)[0]), "+f"((d)[1]), "+f"((d)[2]), "+f"((d)[3]) \
        : "r"((a)[0]), "r"((a)[1]), "r"((a)[2]), "r"((a)[3]), \
          "r"((b)[0]), "r"((b)[1]))

// ---------------- fp32 -> packed bf16x2 hi/lo split ----------------
__global__ void split_pack(const float* __restrict__ in,
                           uint32_t* __restrict__ oh, uint32_t* __restrict__ ol, int n8)
{
    int i = blockIdx.x * blockDim.x + threadIdx.x;
    if (i >= n8) return;
    float4 a = ((const float4*)in)[2 * i];
    float4 b = ((const float4*)in)[2 * i + 1];
    uint16_t h[8], l[8];
    split_bf16(a.x, h[0], l[0]); split_bf16(a.y, h[1], l[1]);
    split_bf16(a.z, h[2], l[2]); split_bf16(a.w, h[3], l[3]);
    split_bf16(b.x, h[4], l[4]); split_bf16(b.y, h[5], l[5]);
    split_bf16(b.z, h[6], l[6]); split_bf16(b.w, h[7], l[7]);
    uint4 uh = make_uint4(pack2(h[0],h[1]), pack2(h[2],h[3]), pack2(h[4],h[5]), pack2(h[6],h[7]));
    uint4 ul = make_uint4(pack2(l[0],l[1]), pack2(l[2],l[3]), pack2(l[4],l[5]), pack2(l[6],l[7]));
    ((uint4*)oh)[i] = uh;
    ((uint4*)ol)[i] = ul;
}

// ============ packed split-BF16 GEMM: C = A[M,K] * B[N,K]^T ============
// Operands pre-split to bf16x2 hi/lo (pairs along K). cp.async double buffer.
#define STRP 20                             // u32 per row: 16 data + 4 pad (16B-aligned)
#define PART_U32 (128 * STRP)               // 2560
#define BUF_U32  (4 * PART_U32)             // Ah,Al,Bh,Bl
#define GEMM_SMEM (2 * BUF_U32 * 4)         // 81920 B

__device__ __forceinline__ void cpa16(uint32_t sa, const void* ga) {
    asm volatile("cp.async.cg.shared.global [%0], [%1], 16;" :: "r"(sa), "l"(ga));
}
#define CP_COMMIT() asm volatile("cp.async.commit_group;" ::: "memory")

__device__ __forceinline__ uint32_t smem_u32p(const void* p) {
    uint32_t a;
    asm("{ .reg .u64 t; cvta.to.shared.u64 t, %1; cvt.u32.u64 %0, t; }" : "=r"(a) : "l"(p));
    return a;
}

__global__ __launch_bounds__(256, 2) void gemm_bf16_packed(
    int M, int N, int K,
    const uint32_t* __restrict__ Ah, const uint32_t* __restrict__ Al,
    const uint32_t* __restrict__ Bh0, const uint32_t* __restrict__ Bl0,
    const uint32_t* __restrict__ Bh1, const uint32_t* __restrict__ Bl1,
    float* __restrict__ C0, float* __restrict__ C1)
{
    extern __shared__ uint32_t s32[];
    const uint32_t sb = smem_u32p(s32);
    const uint32_t* Bh = blockIdx.z ? Bh1 : Bh0;
    const uint32_t* Bl = blockIdx.z ? Bl1 : Bl0;
    float*          C  = blockIdx.z ? C1  : C0;

    const int tid    = threadIdx.x;
    const int wid    = tid >> 5;
    const int lane   = tid & 31;
    const int quad   = lane >> 2;
    const int tq     = lane & 3;
    const int warp_m = wid & 3;
    const int warp_n = wid >> 2;
    const int m0 = blockIdx.y << 7;
    const int n0 = blockIdx.x << 7;
    const int K2 = K >> 1;

    const uint32_t* pAh = Ah + (size_t)m0 * K2;
    const uint32_t* pAl = Al + (size_t)m0 * K2;
    const uint32_t* pBh = Bh + (size_t)n0 * K2;
    const uint32_t* pBl = Bl + (size_t)n0 * K2;

    const int r0_ = tid >> 2;
    const int r1_ = 64 + r0_;
    const int qd  = (tid & 3) * 4;      // u32 offset of 16B chunk within row

#define LOADP(it, buf) do { \
    int kp = (it) * 16; \
    uint32_t sbase = sb + (uint32_t)(buf) * BUF_U32 * 4u; \
    cpa16(sbase + (uint32_t)(0*PART_U32 + r0_*STRP + qd)*4u, pAh + (size_t)r0_*K2 + kp + qd); \
    cpa16(sbase + (uint32_t)(0*PART_U32 + r1_*STRP + qd)*4u, pAh + (size_t)r1_*K2 + kp + qd); \
    cpa16(sbase + (uint32_t)(1*PART_U32 + r0_*STRP + qd)*4u, pAl + (size_t)r0_*K2 + kp + qd); \
    cpa16(sbase + (uint32_t)(1*PART_U32 + r1_*STRP + qd)*4u, pAl + (size_t)r1_*K2 + kp + qd); \
    cpa16(sbase + (uint32_t)(2*PART_U32 + r0_*STRP + qd)*4u, pBh + (size_t)r0_*K2 + kp + qd); \
    cpa16(sbase + (uint32_t)(2*PART_U32 + r1_*STRP + qd)*4u, pBh + (size_t)r1_*K2 + kp + qd); \
    cpa16(sbase + (uint32_t)(3*PART_U32 + r0_*STRP + qd)*4u, pBl + (size_t)r0_*K2 + kp + qd); \
    cpa16(sbase + (uint32_t)(3*PART_U32 + r1_*STRP + qd)*4u, pBl + (size_t)r1_*K2 + kp + qd); \
    CP_COMMIT(); \
} while (0)

    float acc[2][8][4];
#pragma unroll
    for (int mf = 0; mf < 2; mf++)
#pragma unroll
        for (int nf = 0; nf < 8; nf++)
#pragma unroll
            for (int r = 0; r < 4; r++) acc[mf][nf][r] = 0.f;

    const int NT = K / 32;

    LOADP(0, 0);

    for (int it = 0; it < NT; ++it) {
        if (it + 1 < NT) {
            LOADP(it + 1, (it + 1) & 1);
            asm volatile("cp.async.wait_group 1;" ::: "memory");
        } else {
            asm volatile("cp.async.wait_group 0;" ::: "memory");
        }
        __syncthreads();

        const uint32_t* sAh = s32 + (it & 1) * BUF_U32;
        const uint32_t* sAl = sAh + PART_U32;
        const uint32_t* sBh = sAl + PART_U32;
        const uint32_t* sBl = sBh + PART_U32;

#pragma unroll
        for (int ks = 0; ks < 2; ks++) {
            const int kb = ks * 8;
            uint32_t ah[2][4], al[2][4];
#pragma unroll
            for (int mf = 0; mf < 2; mf++) {
                int r = warp_m * 32 + mf * 16 + quad;
                ah[mf][0] = sAh[(r    ) * STRP + kb + tq];
                ah[mf][1] = sAh[(r + 8) * STRP + kb + tq];
                ah[mf][2] = sAh[(r    ) * STRP + kb + tq + 4];
                ah[mf][3] = sAh[(r + 8) * STRP + kb + tq + 4];
                al[mf][0] = sAl[(r    ) * STRP + kb + tq];
                al[mf][1] = sAl[(r + 8) * STRP + kb + tq];
                al[mf][2] = sAl[(r    ) * STRP + kb + tq + 4];
                al[mf][3] = sAl[(r + 8) * STRP + kb + tq + 4];
            }
#pragma unroll
            for (int nf = 0; nf < 8; nf++) {
                int c = warp_n * 64 + nf * 8 + quad;
                uint32_t bh[2], bl[2];
                bh[0] = sBh[c * STRP + kb + tq];
                bh[1] = sBh[c * STRP + kb + tq + 4];
                bl[0] = sBl[c * STRP + kb + tq];
                bl[1] = sBl[c * STRP + kb + tq + 4];
#pragma unroll
                for (int mf = 0; mf < 2; mf++) {
                    MMA_BF16(acc[mf][nf], ah[mf], bh);
                    MMA_BF16(acc[mf][nf], ah[mf], bl);
                    MMA_BF16(acc[mf][nf], al[mf], bh);
                }
            }
        }
        __syncthreads();
    }

#pragma unroll
    for (int mf = 0; mf < 2; mf++) {
        int row = m0 + warp_m * 32 + mf * 16 + quad;
#pragma unroll
        for (int nf = 0; nf < 8; nf++) {
            int col = n0 + warp_n * 64 + nf * 8 + tq * 2;
            *(float2*)(C + (size_t)row * N + col)       = make_float2(acc[mf][nf][0], acc[mf][nf][1]);
            *(float2*)(C + (size_t)(row + 8) * N + col) = make_float2(acc[mf][nf][2], acc[mf][nf][3]);
        }
    }
#undef LOADP
}

// ---------------- fused RMSNorm + RoPE ----------------
__global__ void rmsnorm_rope(float* __restrict__ buf, const float* __restrict__ gamma,
                             int nrows, int heads)
{
    int gw   = (int)((blockIdx.x * blockDim.x + threadIdx.x) >> 5);
    int lane = threadIdx.x & 31;
    if (gw >= nrows) return;
    int bt = gw / heads;
    int h  = gw - bt * heads;
    int t  = bt & (T_SEQ - 1);

    float* row = buf + (size_t)bt * heads * HD + (size_t)h * HD;

    float v[8];
    *(float4*)&v[0] = *(const float4*)(row + lane * 8);
    *(float4*)&v[4] = *(const float4*)(row + lane * 8 + 4);

    float ss = 0.f;
#pragma unroll
    for (int i = 0; i < 8; i++) ss += v[i] * v[i];
#pragma unroll
    for (int o = 16; o > 0; o >>= 1) ss += __shfl_xor_sync(0xffffffffu, ss, o);

    float r = rsqrtf(ss * (1.0f / HD) + 1e-6f);

    float g[8];
    *(float4*)&g[0] = *(const float4*)(gamma + lane * 8);
    *(float4*)&g[4] = *(const float4*)(gamma + lane * 8 + 4);

    float invf[4];
    *(float4*)invf = *(const float4*)(g_invf + lane * 4);

    float tf = (float)t;
#pragma unroll
    for (int p = 0; p < 4; p++) {
        float ang = tf * invf[p];
        float c, s;
        sincosf(ang, &s, &c);
        float x0 = v[2 * p]     * r * g[2 * p];
        float x1 = v[2 * p + 1] * r * g[2 * p + 1];
        v[2 * p]     = x0 * c - x1 * s;
        v[2 * p + 1] = x0 * s + x1 * c;
    }

    *(float4*)(row + lane * 8)     = *(float4*)&v[0];
    *(float4*)(row + lane * 8 + 4) = *(float4*)&v[4];
}

// =========== sliding-window flash attention, split-bf16 mma.sync ===========
#define AQ_STR 132
#define AV_STR 36
#define VS_STR 261
#define ATTN_SMEM_U32 (2*64*AQ_STR + 2*9216 + 2*64*AV_STR)
#define ATTN_SMEM (ATTN_SMEM_U32*4 + 32*VS_STR*4 + (256+192)*4)   // 194944 B

__global__ __launch_bounds__(256, 1) void attn_swa_mma(
    const float* __restrict__ Q, const float* __restrict__ Kg,
    const float* __restrict__ Vg,
    uint32_t* __restrict__ Oh, uint32_t* __restrict__ Ol)
{
    extern __shared__ uint32_t s[];
    uint32_t* Qh  = s;
    uint32_t* Ql  = Qh + 64 * AQ_STR;
    uint32_t* KVh = Ql + 64 * AQ_STR;
    uint32_t* KVl = KVh + 9216;
    uint32_t* Ph  = KVl + 9216;
    uint32_t* Pl  = Ph + 64 * AV_STR;
    float* Vst    = (float*)(Pl + 64 * AV_STR);
    float* red    = Vst + 32 * VS_STR;
    float* m_s    = red + 256;
    float* l_s    = m_s + 64;
    float* corr_s = l_s + 64;

    const int tid  = threadIdx.x;
    const int wid  = tid >> 5, lane = tid & 31, quad = lane >> 2, tq = lane & 3;
    const int wm   = wid & 1, wn = wid >> 1;
    const int qt   = blockIdx.x & 63;
    const int h    = (blockIdx.x >> 6) & 3;
    const int b    = blockIdx.x >> 8;
    const int q0   = qt << 6;

    const float* qbase = Q  + ((size_t)(b * T_SEQ + q0)) * CDIM + (size_t)h * HD;
    const float* kbase = Kg + (size_t)b * T_SEQ * HD;
    const float* vbase = Vg + (size_t)b * T_SEQ * HD;

#pragma unroll
    for (int i = 0; i < 16; i++) {
        int f = i * 256 + tid, row = f >> 6, c4 = f & 63;
        float4 v4 = *(const float4*)(qbase + (size_t)row * CDIM + c4 * 4);
        uint16_t h0,h1,h2,h3,l0,l1,l2,l3;
        split_bf16(v4.x,h0,l0); split_bf16(v4.y,h1,l1);
        split_bf16(v4.z,h2,l2); split_bf16(v4.w,h3,l3);
        int o = row * AQ_STR + c4 * 2;
        Qh[o] = pack2(h0,h1); Qh[o+1] = pack2(h2,h3);
        Ql[o] = pack2(l0,l1); Ql[o+1] = pack2(l2,l3);
    }
    if (tid < 64) { m_s[tid] = -1e30f; l_s[tid] = 0.f; }

    float oacc[2][8][4];
#pragma unroll
    for (int mf = 0; mf < 2; mf++)
#pragma unroll
        for (int nf = 0; nf < 8; nf++)
#pragma unroll
            for (int r = 0; r < 4; r++) oacc[mf][nf][r] = 0.f;

    int kt0 = q0 - WIN; if (kt0 < 0) kt0 = 0;

    for (int kt = kt0; kt <= q0; kt += 64) {
        __syncthreads();   // A

#pragma unroll
        for (int i = 0; i < 16; i++) {
            int f = i * 256 + tid, row = f >> 6, c4 = f & 63;
            float4 v4 = *(const float4*)(kbase + (size_t)(kt + row) * HD + c4 * 4);
            uint16_t h0,h1,h2,h3,l0,l1,l2,l3;
            split_bf16(v4.x,h0,l0); split_bf16(v4.y,h1,l1);
            split_bf16(v4.z,h2,l2); split_bf16(v4.w,h3,l3);
            int o = row * AQ_STR + c4 * 2;
            KVh[o] = pack2(h0,h1); KVh[o+1] = pack2(h2,h3);
            KVl[o] = pack2(l0,l1); KVl[o+1] = pack2(l2,l3);
        }
        __syncthreads();   // B

        float sacc[2][2][4];
#pragma unroll
        for (int mf = 0; mf < 2; mf++)
#pragma unroll
            for (int nf = 0; nf < 2; nf++)
#pragma unroll
                for (int r = 0; r < 4; r++) sacc[mf][nf][r] = 0.f;

#pragma unroll
        for (int ks = 0; ks < 16; ks++) {
            const int kb = ks * 8;
            uint32_t ah[2][4], al[2][4];
#pragma unroll
            for (int mf = 0; mf < 2; mf++) {
                int r = wm * 32 + mf * 16 + quad;
                ah[mf][0] = Qh[(r    ) * AQ_STR + kb + tq];
                ah[mf][1] = Qh[(r + 8) * AQ_STR + kb + tq];
                ah[mf][2] = Qh[(r    ) * AQ_STR + kb + tq + 4];
                ah[mf][3] = Qh[(r + 8) * AQ_STR + kb + tq + 4];
                al[mf][0] = Ql[(r    ) * AQ_STR + kb + tq];
                al[mf][1] = Ql[(r + 8) * AQ_STR + kb + tq];
                al[mf][2] = Ql[(r    ) * AQ_STR + kb + tq + 4];
                al[mf][3] = Ql[(r + 8) * AQ_STR + kb + tq + 4];
            }
#pragma unroll
            for (int nf = 0; nf < 2; nf++) {
                int c = wn * 16 + nf * 8 + quad;
                uint32_t bh[2], bl[2];
                bh[0] = KVh[c * AQ_STR + kb + tq];
                bh[1] = KVh[c * AQ_STR + kb + tq + 4];
                bl[0] = KVl[c * AQ_STR + kb + tq];
                bl[1] = KVl[c * AQ_STR + kb + tq + 4];
#pragma unroll
                for (int mf = 0; mf < 2; mf++) {
                    MMA_BF16(sacc[mf][nf], ah[mf], bh);
                    MMA_BF16(sacc[mf][nf], ah[mf], bl);
                    MMA_BF16(sacc[mf][nf], al[mf], bh);
                }
            }
        }

#pragma unroll
        for (int mf = 0; mf < 2; mf++)
#pragma unroll
            for (int half = 0; half < 2; half++) {
                int rowl = wm * 32 + mf * 16 + quad + half * 8;
                int irow = q0 + rowl;
                float mt = -1e30f;
#pragma unroll
                for (int nf = 0; nf < 2; nf++)
#pragma unroll
                    for (int p = 0; p < 2; p++) {
                        int j = kt + wn * 16 + nf * 8 + tq * 2 + p;
                        bool ok = (j <= irow) && (j >= irow - WIN);
                        float x = ok ? sacc[mf][nf][half * 2 + p] * 0.0625f : -1e30f;
                        sacc[mf][nf][half * 2 + p] = x;
                        mt = fmaxf(mt, x);
                    }
                mt = fmaxf(mt, __shfl_xor_sync(0xffffffffu, mt, 1));
                mt = fmaxf(mt, __shfl_xor_sync(0xffffffffu, mt, 2));
                if (tq == 0) red[wn * 64 + rowl] = mt;
            }
        __syncthreads();   // C

        if (wid < 2 && tq == 0) {
#pragma unroll
            for (int mf = 0; mf < 2; mf++)
#pragma unroll
                for (int half = 0; half < 2; half++) {
                    int rowl = wid * 32 + mf * 16 + quad + half * 8;
                    float mt = fmaxf(fmaxf(red[rowl], red[64 + rowl]),
                                     fmaxf(red[128 + rowl], red[192 + rowl]));
                    float mo = m_s[rowl];
                    float mn = fmaxf(mo, mt);
                    corr_s[rowl] = __expf(mo - mn);
                    m_s[rowl]    = mn;
                }
        }
        __syncthreads();   // D

#pragma unroll
        for (int mf = 0; mf < 2; mf++)
#pragma unroll
            for (int half = 0; half < 2; half++) {
                int rowl = wm * 32 + mf * 16 + quad + half * 8;
                float mn = m_s[rowl];
                float rs = 0.f;
#pragma unroll
                for (int nf = 0; nf < 2; nf++) {
                    float p0 = __expf(sacc[mf][nf][half * 2 + 0] - mn);
                    float p1 = __expf(sacc[mf][nf][half * 2 + 1] - mn);
                    rs += p0 + p1;
                    uint16_t h0, l0, h1, l1;
                    split_bf16(p0, h0, l0); split_bf16(p1, h1, l1);
                    int o = rowl * AV_STR + wn * 8 + nf * 4 + tq;
                    Ph[o] = pack2(h0, h1);
                    Pl[o] = pack2(l0, l1);
                }
                rs += __shfl_xor_sync(0xffffffffu, rs, 1);
                rs += __shfl_xor_sync(0xffffffffu, rs, 2);
                if (tq == 0) red[wn * 64 + rowl] = rs;
            }
        __syncthreads();   // E

        if (wid < 2 && tq == 0) {
#pragma unroll
            for (int mf = 0; mf < 2; mf++)
#pragma unroll
                for (int half = 0; half < 2; half++) {
                    int rowl = wid * 32 + mf * 16 + quad + half * 8;
                    l_s[rowl] = l_s[rowl] * corr_s[rowl] +
                                red[rowl] + red[64 + rowl] + red[128 + rowl] + red[192 + rowl];
                }
        }
#pragma unroll
        for (int mf = 0; mf < 2; mf++) {
            int r0 = wm * 32 + mf * 16 + quad;
            float c0 = corr_s[r0], c1 = corr_s[r0 + 8];
#pragma unroll
            for (int nf = 0; nf < 8; nf++) {
                oacc[mf][nf][0] *= c0; oacc[mf][nf][1] *= c0;
                oacc[mf][nf][2] *= c1; oacc[mf][nf][3] *= c1;
            }
        }

#pragma unroll
        for (int hf = 0; hf < 2; hf++) {
            __syncthreads();   // F/H
#pragma unroll
            for (int i = 0; i < 8; i++) {
                int f = i * 256 + tid, row = f >> 6, c4 = f & 63;
                float4 v4 = *(const float4*)(vbase + (size_t)(kt + hf * 32 + row) * HD + c4 * 4);
                float* dst = Vst + row * VS_STR + c4 * 4;
                dst[0] = v4.x; dst[1] = v4.y; dst[2] = v4.z; dst[3] = v4.w;
            }
            __syncthreads();   // G/I
            {
                int j  = lane;
                int d0 = wid * 32;
                int key = hf * 32 + j;
                uint16_t* KVh16 = (uint16_t*)KVh;
                uint16_t* KVl16 = (uint16_t*)KVl;
#pragma unroll
                for (int i = 0; i < 32; i++) {
                    int d = d0 + i;
                    float x = Vst[j * VS_STR + d];
                    uint16_t hh, ll;
                    split_bf16(x, hh, ll);
                    int word = d * AV_STR + (key >> 1);
                    KVh16[word * 2 + (key & 1)] = hh;
                    KVl16[word * 2 + (key & 1)] = ll;
                }
            }
        }
        __syncthreads();   // J

#pragma unroll
        for (int kk = 0; kk < 4; kk++) {
            const int kb = kk * 8;
            uint32_t pah[2][4], pal[2][4];
#pragma unroll
            for (int mf = 0; mf < 2; mf++) {
                int r = wm * 32 + mf * 16 + quad;
                pah[mf][0] = Ph[(r    ) * AV_STR + kb + tq];
                pah[mf][1] = Ph[(r + 8) * AV_STR + kb + tq];
                pah[mf][2] = Ph[(r    ) * AV_STR + kb + tq + 4];
                pah[mf][3] = Ph[(r + 8) * AV_STR + kb + tq + 4];
                pal[mf][0] = Pl[(r    ) * AV_STR + kb + tq];
                pal[mf][1] = Pl[(r + 8) * AV_STR + kb + tq];
                pal[mf][2] = Pl[(r    ) * AV_STR + kb + tq + 4];
                pal[mf][3] = Pl[(r + 8) * AV_STR + kb + tq + 4];
            }
#pragma unroll
            for (int nf = 0; nf < 8; nf++) {
                int c = wn * 64 + nf * 8 + quad;
                uint32_t vbh[2], vbl[2];
                vbh[0] = KVh[c * AV_STR + kb + tq];
                vbh[1] = KVh[c * AV_STR + kb + tq + 4];
                vbl[0] = KVl[c * AV_STR + kb + tq];
                vbl[1] = KVl[c * AV_STR + kb + tq + 4];
#pragma unroll
                for (int mf = 0; mf < 2; mf++) {
                    MMA_BF16(oacc[mf][nf], pah[mf], vbh);
                    MMA_BF16(oacc[mf][nf], pah[mf], vbl);
                    MMA_BF16(oacc[mf][nf], pal[mf], vbh);
                }
            }
        }
    }

    // ---- epilogue: write ao directly as packed bf16x2 hi/lo ----
#pragma unroll
    for (int mf = 0; mf < 2; mf++) {
        int r0 = wm * 32 + mf * 16 + quad;
        float i0 = 1.f / l_s[r0], i1 = 1.f / l_s[r0 + 8];
        size_t base0 = ((size_t)(b * T_SEQ + q0 + r0)) * (CDIM / 2) + h * (HD / 2);
        size_t base1 = base0 + 8 * (CDIM / 2);
#pragma unroll
        for (int nf = 0; nf < 8; nf++) {
            int cp_ = wn * 32 + nf * 4 + tq;
            uint16_t h0, l0, h1, l1;
            split_bf16(oacc[mf][nf][0] * i0, h0, l0);
            split_bf16(oacc[mf][nf][1] * i0, h1, l1);
            Oh[base0 + cp_] = pack2(h0, h1);
            Ol[base0 + cp_] = pack2(l0, l1);
            split_bf16(oacc[mf][nf][2] * i1, h0, l0);
            split_bf16(oacc[mf][nf][3] * i1, h1, l1);
            Oh[base1 + cp_] = pack2(h0, h1);
            Ol[base1 + cp_] = pack2(l0, l1);
        }
    }
}

// ---------------- launch ----------------
extern "C" void kernel_launch(void* const* d_in, const int* in_sizes, int n_in,
                              void* d_out, int out_size)
{
    const float* x  = (const float*)d_in[0];
    const float* Wq = (const float*)d_in[1];
    const float* Wk = (const float*)d_in[2];
    const float* Wv = (const float*)d_in[3];
    const float* Wo = (const float*)d_in[4];
    const float* qg = (const float*)d_in[5];
    const float* kg = (const float*)d_in[6];
    float* out = (float*)d_out;

    float *q, *k, *v;
    uint32_t *xh, *xl, *aoh, *aol, *wqh, *wql, *wkh, *wkl, *wvh, *wvl, *woh, *wol;
    cudaGetSymbolAddress((void**)&q,   g_q);
    cudaGetSymbolAddress((void**)&k,   g_k);
    cudaGetSymbolAddress((void**)&v,   g_v);
    cudaGetSymbolAddress((void**)&xh,  g_xh);
    cudaGetSymbolAddress((void**)&xl,  g_xl);
    cudaGetSymbolAddress((void**)&aoh, g_aoh);
    cudaGetSymbolAddress((void**)&aol, g_aol);
    cudaGetSymbolAddress((void**)&wqh, g_wqh);
    cudaGetSymbolAddress((void**)&wql, g_wql);
    cudaGetSymbolAddress((void**)&wkh, g_wkh);
    cudaGetSymbolAddress((void**)&wkl, g_wkl);
    cudaGetSymbolAddress((void**)&wvh, g_wvh);
    cudaGetSymbolAddress((void**)&wvl, g_wvl);
    cudaGetSymbolAddress((void**)&woh, g_woh);
    cudaGetSymbolAddress((void**)&wol, g_wol);

    const int M = BATCH * T_SEQ;   // 8192

    init_invf<<<1, 128>>>();

    // pre-split all GEMM operands to packed bf16x2 hi/lo
    split_pack<<<(M * CDIM / 8 + 255) / 256, 256>>>(x,  xh,  xl,  M * CDIM / 8);
    split_pack<<<(CDIM * CDIM / 8 + 255) / 256, 256>>>(Wq, wqh, wql, CDIM * CDIM / 8);
    split_pack<<<(HD * CDIM / 8 + 255) / 256, 256>>>(Wk, wkh, wkl, HD * CDIM / 8);
    split_pack<<<(HD * CDIM / 8 + 255) / 256, 256>>>(Wv, wvh, wvl, HD * CDIM / 8);
    split_pack<<<(CDIM * CDIM / 8 + 255) / 256, 256>>>(Wo, woh, wol, CDIM * CDIM / 8);

    cudaFuncSetAttribute(gemm_bf16_packed, cudaFuncAttributeMaxDynamicSharedMemorySize, GEMM_SMEM);

    // Q projection
    gemm_bf16_packed<<<dim3(CDIM / 128, M / 128, 1), 256, GEMM_SMEM>>>(
        M, CDIM, CDIM, xh, xl, wqh, wql, wqh, wql, q, q);
    // K and V projections fused (z selects weight/output)
    gemm_bf16_packed<<<dim3(HD / 128, M / 128, 2), 256, GEMM_SMEM>>>(
        M, HD, CDIM, xh, xl, wkh, wkl, wvh, wvl, k, v);

    rmsnorm_rope<<<(M * NH) / 8, 256>>>(q, qg, M * NH, NH);
    rmsnorm_rope<<<M / 8, 256>>>(k, kg, M, 1);

    cudaFuncSetAttribute(attn_swa_mma, cudaFuncAttributeMaxDynamicSharedMemorySize, ATTN_SMEM);
    attn_swa_mma<<<BATCH * NH * (T_SEQ / 64), 256, ATTN_SMEM>>>(q, k, v, aoh, aol);

    // output projection (consumes packed ao from attention epilogue)
    gemm_bf16_packed<<<dim3(CDIM / 128, M / 128, 1), 256, GEMM_SMEM>>>(
        M, CDIM, CDIM, aoh, aol, woh, wol, woh, wol, out, out);
}

// round 8
// speedup vs baseline: 3.9512x; 1.2319x over previous
#include <cuda_runtime.h>
#include <math.h>
#include <stdint.h>

#define T_SEQ 4096
#define BATCH 2
#define CDIM  1024
#define HD    256
#define NH    4
#define WIN   512

// ---------------- scratch (static device globals; no allocation) ----------------
__device__ float    g_q [(size_t)BATCH * T_SEQ * CDIM];
__device__ float    g_k [(size_t)BATCH * T_SEQ * HD];
__device__ float    g_v [(size_t)BATCH * T_SEQ * HD];
__device__ float    g_invf[HD / 2];
// packed bf16x2 hi/lo operand buffers
__device__ uint32_t g_xh [(size_t)BATCH * T_SEQ * CDIM / 2];
__device__ uint32_t g_xl [(size_t)BATCH * T_SEQ * CDIM / 2];
__device__ uint32_t g_aoh[(size_t)BATCH * T_SEQ * CDIM / 2];
__device__ uint32_t g_aol[(size_t)BATCH * T_SEQ * CDIM / 2];
__device__ uint32_t g_wqh[CDIM * CDIM / 2];
__device__ uint32_t g_wql[CDIM * CDIM / 2];
__device__ uint32_t g_wkh[HD * CDIM / 2];
__device__ uint32_t g_wkl[HD * CDIM / 2];
__device__ uint32_t g_wvh[HD * CDIM / 2];
__device__ uint32_t g_wvl[HD * CDIM / 2];
__device__ uint32_t g_woh[CDIM * CDIM / 2];
__device__ uint32_t g_wol[CDIM * CDIM / 2];
// pre-split attention operands
__device__ uint32_t g_qph[(size_t)BATCH * T_SEQ * CDIM / 2];
__device__ uint32_t g_qpl[(size_t)BATCH * T_SEQ * CDIM / 2];
__device__ uint32_t g_kph[(size_t)BATCH * T_SEQ * HD / 2];
__device__ uint32_t g_kpl[(size_t)BATCH * T_SEQ * HD / 2];
__device__ uint32_t g_vth[(size_t)BATCH * HD * T_SEQ / 2];
__device__ uint32_t g_vtl[(size_t)BATCH * HD * T_SEQ / 2];

// ---------------- RoPE inv_freq table ----------------
__global__ void init_invf()
{
    int i = threadIdx.x;
    float e = (float)(2 * i) * (1.0f / HD);
    g_invf[i] = (float)pow(1000000.0, -(double)e);
}

// ---------------- common helpers ----------------
__device__ __forceinline__ void split_bf16(float x, uint16_t& h, uint16_t& l) {
    asm("cvt.rn.bf16.f32 %0, %1;" : "=h"(h) : "f"(x));
    float r = x - __uint_as_float((uint32_t)h << 16);   // exact
    asm("cvt.rn.bf16.f32 %0, %1;" : "=h"(l) : "f"(r));
}
__device__ __forceinline__ uint32_t pack2(uint16_t a, uint16_t b) {
    return (uint32_t)a | ((uint32_t)b << 16);
}
__device__ __forceinline__ uint32_t smem_u32p(const void* p) {
    uint32_t a;
    asm("{ .reg .u64 t; cvta.to.shared.u64 t, %1; cvt.u32.u64 %0, t; }" : "=r"(a) : "l"(p));
    return a;
}

#define MMA_BF16(d, a, b) \
    asm volatile("mma.sync.aligned.m16n8k16.row.col.f32.bf16.bf16.f32 " \
        "{%0,%1,%2,%3}, {%4,%5,%6,%7}, {%8,%9}, {%0,%1,%2,%3};" \
        : "+f"((d)[0]), "+f"((d)[1]), "+f"((d)[2]), "+f"((d)[3]) \
        : "r"((a)[0]), "r"((a)[1]), "r"((a)[2]), "r"((a)[3]), \
          "r"((b)[0]), "r"((b)[1]))

#define LDSM4(r0, r1, r2, r3, a) \
    asm volatile("ldmatrix.sync.aligned.m8n8.x4.shared.b16 {%0,%1,%2,%3}, [%4];" \
        : "=r"(r0), "=r"(r1), "=r"(r2), "=r"(r3) : "r"(a))

__device__ __forceinline__ void cpa16(uint32_t sa, const void* ga) {
    asm volatile("cp.async.cg.shared.global [%0], [%1], 16;" :: "r"(sa), "l"(ga));
}
#define CP_COMMIT() asm volatile("cp.async.commit_group;" ::: "memory")
#define CP_WAIT0()  asm volatile("cp.async.wait_group 0;" ::: "memory")

// ---------------- fp32 -> packed bf16x2 hi/lo split ----------------
__global__ void split_pack(const float* __restrict__ in,
                           uint32_t* __restrict__ oh, uint32_t* __restrict__ ol, int n8)
{
    int i = blockIdx.x * blockDim.x + threadIdx.x;
    if (i >= n8) return;
    float4 a = ((const float4*)in)[2 * i];
    float4 b = ((const float4*)in)[2 * i + 1];
    uint16_t h[8], l[8];
    split_bf16(a.x, h[0], l[0]); split_bf16(a.y, h[1], l[1]);
    split_bf16(a.z, h[2], l[2]); split_bf16(a.w, h[3], l[3]);
    split_bf16(b.x, h[4], l[4]); split_bf16(b.y, h[5], l[5]);
    split_bf16(b.z, h[6], l[6]); split_bf16(b.w, h[7], l[7]);
    ((uint4*)oh)[i] = make_uint4(pack2(h[0],h[1]), pack2(h[2],h[3]), pack2(h[4],h[5]), pack2(h[6],h[7]));
    ((uint4*)ol)[i] = make_uint4(pack2(l[0],l[1]), pack2(l[2],l[3]), pack2(l[4],l[5]), pack2(l[6],l[7]));
}

// ============ packed split-BF16 GEMM (ldmatrix fragments) ============
#define STRP 20
#define PART_U32 (128 * STRP)
#define BUF_U32  (4 * PART_U32)
#define GEMM_SMEM (2 * BUF_U32 * 4)

__global__ __launch_bounds__(256, 2) void gemm_bf16_packed(
    int M, int N, int K,
    const uint32_t* __restrict__ Ah, const uint32_t* __restrict__ Al,
    const uint32_t* __restrict__ Bh0, const uint32_t* __restrict__ Bl0,
    const uint32_t* __restrict__ Bh1, const uint32_t* __restrict__ Bl1,
    float* __restrict__ C0, float* __restrict__ C1)
{
    extern __shared__ uint32_t s32[];
    const uint32_t sb = smem_u32p(s32);
    const uint32_t* Bh = blockIdx.z ? Bh1 : Bh0;
    const uint32_t* Bl = blockIdx.z ? Bl1 : Bl0;
    float*          C  = blockIdx.z ? C1  : C0;

    const int tid    = threadIdx.x;
    const int wid    = tid >> 5;
    const int lane   = tid & 31;
    const int quad   = lane >> 2;
    const int tq     = lane & 3;
    const int warp_m = wid & 3;
    const int warp_n = wid >> 2;
    const int m0 = blockIdx.y << 7;
    const int n0 = blockIdx.x << 7;
    const int K2 = K >> 1;

    // ldmatrix lane-derived constants
    const int jm   = lane >> 3, jr = lane & 7;
    const int a_ro = (jm & 1) * 8 + jr;
    const int a_ko = (jm >> 1) * 4;
    const int b_go = jm >> 1;
    const int b_ko = (jm & 1) * 4;

    const uint32_t* pAh = Ah + (size_t)m0 * K2;
    const uint32_t* pAl = Al + (size_t)m0 * K2;
    const uint32_t* pBh = Bh + (size_t)n0 * K2;
    const uint32_t* pBl = Bl + (size_t)n0 * K2;

    const int r0_ = tid >> 2;
    const int r1_ = 64 + r0_;
    const int qd  = (tid & 3) * 4;

#define LOADP(it, buf) do { \
    int kp = (it) * 16; \
    uint32_t sbase = sb + (uint32_t)(buf) * BUF_U32 * 4u; \
    cpa16(sbase + (uint32_t)(0*PART_U32 + r0_*STRP + qd)*4u, pAh + (size_t)r0_*K2 + kp + qd); \
    cpa16(sbase + (uint32_t)(0*PART_U32 + r1_*STRP + qd)*4u, pAh + (size_t)r1_*K2 + kp + qd); \
    cpa16(sbase + (uint32_t)(1*PART_U32 + r0_*STRP + qd)*4u, pAl + (size_t)r0_*K2 + kp + qd); \
    cpa16(sbase + (uint32_t)(1*PART_U32 + r1_*STRP + qd)*4u, pAl + (size_t)r1_*K2 + kp + qd); \
    cpa16(sbase + (uint32_t)(2*PART_U32 + r0_*STRP + qd)*4u, pBh + (size_t)r0_*K2 + kp + qd); \
    cpa16(sbase + (uint32_t)(2*PART_U32 + r1_*STRP + qd)*4u, pBh + (size_t)r1_*K2 + kp + qd); \
    cpa16(sbase + (uint32_t)(3*PART_U32 + r0_*STRP + qd)*4u, pBl + (size_t)r0_*K2 + kp + qd); \
    cpa16(sbase + (uint32_t)(3*PART_U32 + r1_*STRP + qd)*4u, pBl + (size_t)r1_*K2 + kp + qd); \
    CP_COMMIT(); \
} while (0)

    float acc[2][8][4];
#pragma unroll
    for (int mf = 0; mf < 2; mf++)
#pragma unroll
        for (int nf = 0; nf < 8; nf++)
#pragma unroll
            for (int r = 0; r < 4; r++) acc[mf][nf][r] = 0.f;

    const int NT = K / 32;

    LOADP(0, 0);

    for (int it = 0; it < NT; ++it) {
        if (it + 1 < NT) {
            LOADP(it + 1, (it + 1) & 1);
            asm volatile("cp.async.wait_group 1;" ::: "memory");
        } else {
            asm volatile("cp.async.wait_group 0;" ::: "memory");
        }
        __syncthreads();

        const uint32_t sA = sb + (uint32_t)(it & 1) * BUF_U32 * 4u;
        const uint32_t sB = sA + 2u * PART_U32 * 4u;

#pragma unroll
        for (int ks = 0; ks < 2; ks++) {
            const int kb = ks * 8;
            uint32_t ah[2][4], al[2][4];
#pragma unroll
            for (int mf = 0; mf < 2; mf++) {
                uint32_t ar = sA + (uint32_t)((warp_m*32 + mf*16 + a_ro) * STRP + kb + a_ko) * 4u;
                LDSM4(ah[mf][0], ah[mf][1], ah[mf][2], ah[mf][3], ar);
                LDSM4(al[mf][0], al[mf][1], al[mf][2], al[mf][3], ar + PART_U32*4u);
            }
#pragma unroll
            for (int g = 0; g < 4; g++) {
                uint32_t br = sB + (uint32_t)((warp_n*64 + (2*g + b_go)*8 + jr) * STRP + kb + b_ko) * 4u;
                uint32_t b0h[2], b1h[2], b0l[2], b1l[2];
                LDSM4(b0h[0], b0h[1], b1h[0], b1h[1], br);
                LDSM4(b0l[0], b0l[1], b1l[0], b1l[1], br + PART_U32*4u);
#pragma unroll
                for (int mf = 0; mf < 2; mf++) {
                    MMA_BF16(acc[mf][2*g],   ah[mf], b0h);
                    MMA_BF16(acc[mf][2*g],   ah[mf], b0l);
                    MMA_BF16(acc[mf][2*g],   al[mf], b0h);
                    MMA_BF16(acc[mf][2*g+1], ah[mf], b1h);
                    MMA_BF16(acc[mf][2*g+1], ah[mf], b1l);
                    MMA_BF16(acc[mf][2*g+1], al[mf], b1h);
                }
            }
        }
        __syncthreads();
    }

#pragma unroll
    for (int mf = 0; mf < 2; mf++) {
        int row = m0 + warp_m * 32 + mf * 16 + quad;
#pragma unroll
        for (int nf = 0; nf < 8; nf++) {
            int col = n0 + warp_n * 64 + nf * 8 + tq * 2;
            *(float2*)(C + (size_t)row * N + col)       = make_float2(acc[mf][nf][0], acc[mf][nf][1]);
            *(float2*)(C + (size_t)(row + 8) * N + col) = make_float2(acc[mf][nf][2], acc[mf][nf][3]);
        }
    }
#undef LOADP
}

// ---------------- fused RMSNorm + RoPE -> packed bf16x2 hi/lo ----------------
__global__ void rmsnorm_rope_pack(const float* __restrict__ in, const float* __restrict__ gamma,
                                  uint32_t* __restrict__ oh, uint32_t* __restrict__ ol,
                                  int nrows, int heads)
{
    int gw   = (int)((blockIdx.x * blockDim.x + threadIdx.x) >> 5);
    int lane = threadIdx.x & 31;
    if (gw >= nrows) return;
    int bt = gw / heads;
    int t  = bt & (T_SEQ - 1);

    const float* row = in + (size_t)gw * HD;

    float v[8];
    *(float4*)&v[0] = *(const float4*)(row + lane * 8);
    *(float4*)&v[4] = *(const float4*)(row + lane * 8 + 4);

    float ss = 0.f;
#pragma unroll
    for (int i = 0; i < 8; i++) ss += v[i] * v[i];
#pragma unroll
    for (int o = 16; o > 0; o >>= 1) ss += __shfl_xor_sync(0xffffffffu, ss, o);

    float r = rsqrtf(ss * (1.0f / HD) + 1e-6f);

    float g[8];
    *(float4*)&g[0] = *(const float4*)(gamma + lane * 8);
    *(float4*)&g[4] = *(const float4*)(gamma + lane * 8 + 4);

    float invf[4];
    *(float4*)invf = *(const float4*)(g_invf + lane * 4);

    float tf = (float)t;
#pragma unroll
    for (int p = 0; p < 4; p++) {
        float ang = tf * invf[p];
        float c, s;
        sincosf(ang, &s, &c);
        float x0 = v[2 * p]     * r * g[2 * p];
        float x1 = v[2 * p + 1] * r * g[2 * p + 1];
        v[2 * p]     = x0 * c - x1 * s;
        v[2 * p + 1] = x0 * s + x1 * c;
    }

    uint16_t hh[8], ll[8];
#pragma unroll
    for (int i = 0; i < 8; i++) split_bf16(v[i], hh[i], ll[i]);
    size_t ob = (size_t)gw * (HD / 2) + lane * 4;
    *(uint4*)(oh + ob) = make_uint4(pack2(hh[0],hh[1]), pack2(hh[2],hh[3]),
                                    pack2(hh[4],hh[5]), pack2(hh[6],hh[7]));
    *(uint4*)(ol + ob) = make_uint4(pack2(ll[0],ll[1]), pack2(ll[2],ll[3]),
                                    pack2(ll[4],ll[5]), pack2(ll[6],ll[7]));
}

// ---------------- V transpose + split: v[b][t][d] -> Vt[b][d][t-pairs] ----------------
#define VT_SMEM (256 * 69 * 4)
__global__ __launch_bounds__(256) void transpose_split_v(
    const float* __restrict__ v, uint32_t* __restrict__ vth, uint32_t* __restrict__ vtl)
{
    extern __shared__ float st[];
    int b = blockIdx.y, t0 = blockIdx.x * 64;
    int tid = threadIdx.x;
    const float* vb = v + ((size_t)(b * T_SEQ + t0)) * HD;
#pragma unroll
    for (int i = 0; i < 16; i++) {
        int f = i * 256 + tid;
        int t = f >> 6, d4 = (f & 63) * 4;
        float4 x = *(const float4*)(vb + (size_t)t * HD + d4);
        st[(d4 + 0) * 69 + t] = x.x;
        st[(d4 + 1) * 69 + t] = x.y;
        st[(d4 + 2) * 69 + t] = x.z;
        st[(d4 + 3) * 69 + t] = x.w;
    }
    __syncthreads();
    int w = tid >> 5, l = tid & 31;
#pragma unroll
    for (int pass = 0; pass < 32; pass++) {
        int d = pass * 8 + w;
        float x0 = st[d * 69 + 2 * l];
        float x1 = st[d * 69 + 2 * l + 1];
        uint16_t h0, l0, h1, l1;
        split_bf16(x0, h0, l0); split_bf16(x1, h1, l1);
        size_t o = ((size_t)(b * HD + d)) * (T_SEQ / 2) + (t0 >> 1) + l;
        vth[o] = pack2(h0, h1);
        vtl[o] = pack2(l0, l1);
    }
}

// =========== sliding-window flash attention: pre-split operands + ldmatrix ===========
#define AQ_STR 132
#define AV_STR 36
// u32 offsets in smem
#define OFF_QH  0
#define OFF_QL  (64 * AQ_STR)
#define OFF_KVH (2 * 64 * AQ_STR)
#define OFF_KVL (OFF_KVH + 9216)
#define OFF_PH  (OFF_KVL + 9216)
#define OFF_PL  (OFF_PH + 64 * AV_STR)
#define OFF_RED (OFF_PL + 64 * AV_STR)
#define ATTN_U32 (OFF_RED + 256 + 192)
#define ATTN_SMEM (ATTN_U32 * 4)      // 161536 B

__global__ __launch_bounds__(256, 1) void attn_swa_mma(
    const uint32_t* __restrict__ Qph, const uint32_t* __restrict__ Qpl,
    const uint32_t* __restrict__ Kph, const uint32_t* __restrict__ Kpl,
    const uint32_t* __restrict__ Vth, const uint32_t* __restrict__ Vtl,
    uint32_t* __restrict__ Oh, uint32_t* __restrict__ Ol)
{
    extern __shared__ uint32_t s[];
    const uint32_t sb = smem_u32p(s);
    uint32_t* Ph  = s + OFF_PH;
    uint32_t* Pl  = s + OFF_PL;
    float* red    = (float*)(s + OFF_RED);
    float* m_s    = red + 256;
    float* l_s    = m_s + 64;
    float* corr_s = l_s + 64;

    const int tid  = threadIdx.x;
    const int wid  = tid >> 5, lane = tid & 31, quad = lane >> 2, tq = lane & 3;
    const int wm   = wid & 1, wn = wid >> 1;
    const int jm   = lane >> 3, jr = lane & 7;
    const int a_ro = (jm & 1) * 8 + jr;
    const int a_ko = (jm >> 1) * 4;
    const int b_go = jm >> 1;
    const int b_ko = (jm & 1) * 4;
    const int qt   = blockIdx.x & 63;
    const int h    = (blockIdx.x >> 6) & 3;
    const int b    = blockIdx.x >> 8;
    const int q0   = qt << 6;

    const uint32_t* qh_g = Qph + ((size_t)(b * T_SEQ + q0)) * (CDIM / 2) + h * (HD / 2);
    const uint32_t* ql_g = Qpl + ((size_t)(b * T_SEQ + q0)) * (CDIM / 2) + h * (HD / 2);
    const uint32_t* kh_g = Kph + (size_t)b * T_SEQ * (HD / 2);
    const uint32_t* kl_g = Kpl + (size_t)b * T_SEQ * (HD / 2);
    const uint32_t* vh_g = Vth + (size_t)b * HD * (T_SEQ / 2);
    const uint32_t* vl_g = Vtl + (size_t)b * HD * (T_SEQ / 2);

    // ---- Q tile via cp.async ----
#pragma unroll
    for (int i = 0; i < 8; i++) {
        int f = i * 256 + tid, row = f >> 5, c4 = (f & 31) * 4;
        cpa16(sb + (uint32_t)(OFF_QH + row * AQ_STR + c4) * 4u, qh_g + (size_t)row * (CDIM / 2) + c4);
        cpa16(sb + (uint32_t)(OFF_QL + row * AQ_STR + c4) * 4u, ql_g + (size_t)row * (CDIM / 2) + c4);
    }
    CP_COMMIT();
    if (tid < 64) { m_s[tid] = -1e30f; l_s[tid] = 0.f; }
    CP_WAIT0();
    __syncthreads();

    float oacc[2][8][4];
#pragma unroll
    for (int mf = 0; mf < 2; mf++)
#pragma unroll
        for (int nf = 0; nf < 8; nf++)
#pragma unroll
            for (int r = 0; r < 4; r++) oacc[mf][nf][r] = 0.f;

    int kt0 = q0 - WIN; if (kt0 < 0) kt0 = 0;

    for (int kt = kt0; kt <= q0; kt += 64) {
        __syncthreads();   // A: prev PV done reading KV(V)/P

        // ---- K tile via cp.async ----
#pragma unroll
        for (int i = 0; i < 8; i++) {
            int f = i * 256 + tid, row = f >> 5, c4 = (f & 31) * 4;
            cpa16(sb + (uint32_t)(OFF_KVH + row * AQ_STR + c4) * 4u, kh_g + (size_t)(kt + row) * (HD / 2) + c4);
            cpa16(sb + (uint32_t)(OFF_KVL + row * AQ_STR + c4) * 4u, kl_g + (size_t)(kt + row) * (HD / 2) + c4);
        }
        CP_COMMIT();
        CP_WAIT0();
        __syncthreads();   // B

        // ---- S = Q K^T (ldmatrix + split MMA) ----
        float sacc[2][2][4];
#pragma unroll
        for (int mf = 0; mf < 2; mf++)
#pragma unroll
            for (int nf = 0; nf < 2; nf++)
#pragma unroll
                for (int r = 0; r < 4; r++) sacc[mf][nf][r] = 0.f;

#pragma unroll
        for (int ks = 0; ks < 16; ks++) {
            const int kb = ks * 8;
            uint32_t ah[2][4], al[2][4];
#pragma unroll
            for (int mf = 0; mf < 2; mf++) {
                uint32_t ar = sb + (uint32_t)(OFF_QH + (wm*32 + mf*16 + a_ro) * AQ_STR + kb + a_ko) * 4u;
                LDSM4(ah[mf][0], ah[mf][1], ah[mf][2], ah[mf][3], ar);
                LDSM4(al[mf][0], al[mf][1], al[mf][2], al[mf][3], ar + (OFF_QL - OFF_QH) * 4u);
            }
            uint32_t br = sb + (uint32_t)(OFF_KVH + (wn*16 + b_go*8 + jr) * AQ_STR + kb + b_ko) * 4u;
            uint32_t b0h[2], b1h[2], b0l[2], b1l[2];
            LDSM4(b0h[0], b0h[1], b1h[0], b1h[1], br);
            LDSM4(b0l[0], b0l[1], b1l[0], b1l[1], br + (OFF_KVL - OFF_KVH) * 4u);
#pragma unroll
            for (int mf = 0; mf < 2; mf++) {
                MMA_BF16(sacc[mf][0], ah[mf], b0h);
                MMA_BF16(sacc[mf][0], ah[mf], b0l);
                MMA_BF16(sacc[mf][0], al[mf], b0h);
                MMA_BF16(sacc[mf][1], ah[mf], b1h);
                MMA_BF16(sacc[mf][1], ah[mf], b1l);
                MMA_BF16(sacc[mf][1], al[mf], b1h);
            }
        }

        // ---- mask + scale + row max ----
#pragma unroll
        for (int mf = 0; mf < 2; mf++)
#pragma unroll
            for (int half = 0; half < 2; half++) {
                int rowl = wm * 32 + mf * 16 + quad + half * 8;
                int irow = q0 + rowl;
                float mt = -1e30f;
#pragma unroll
                for (int nf = 0; nf < 2; nf++)
#pragma unroll
                    for (int p = 0; p < 2; p++) {
                        int j = kt + wn * 16 + nf * 8 + tq * 2 + p;
                        bool ok = (j <= irow) && (j >= irow - WIN);
                        float x = ok ? sacc[mf][nf][half * 2 + p] * 0.0625f : -1e30f;
                        sacc[mf][nf][half * 2 + p] = x;
                        mt = fmaxf(mt, x);
                    }
                mt = fmaxf(mt, __shfl_xor_sync(0xffffffffu, mt, 1));
                mt = fmaxf(mt, __shfl_xor_sync(0xffffffffu, mt, 2));
                if (tq == 0) red[wn * 64 + rowl] = mt;
            }
        __syncthreads();   // C

        // ---- V^T tile via cp.async (overlaps softmax) ----
#pragma unroll
        for (int i = 0; i < 8; i++) {
            int f = i * 256 + tid, d = f >> 3, c4 = (f & 7) * 4;
            cpa16(sb + (uint32_t)(OFF_KVH + d * AV_STR + c4) * 4u, vh_g + (size_t)d * (T_SEQ / 2) + (kt >> 1) + c4);
            cpa16(sb + (uint32_t)(OFF_KVL + d * AV_STR + c4) * 4u, vl_g + (size_t)d * (T_SEQ / 2) + (kt >> 1) + c4);
        }
        CP_COMMIT();

        if (wid < 2 && tq == 0) {
#pragma unroll
            for (int mf = 0; mf < 2; mf++)
#pragma unroll
                for (int half = 0; half < 2; half++) {
                    int rowl = wid * 32 + mf * 16 + quad + half * 8;
                    float mt = fmaxf(fmaxf(red[rowl], red[64 + rowl]),
                                     fmaxf(red[128 + rowl], red[192 + rowl]));
                    float mo = m_s[rowl];
                    float mn = fmaxf(mo, mt);
                    corr_s[rowl] = __expf(mo - mn);
                    m_s[rowl]    = mn;
                }
        }
        __syncthreads();   // D

        // ---- P = exp(S - m); split -> Ph/Pl; row sums ----
#pragma unroll
        for (int mf = 0; mf < 2; mf++)
#pragma unroll
            for (int half = 0; half < 2; half++) {
                int rowl = wm * 32 + mf * 16 + quad + half * 8;
                float mn = m_s[rowl];
                float rs = 0.f;
#pragma unroll
                for (int nf = 0; nf < 2; nf++) {
                    float p0 = __expf(sacc[mf][nf][half * 2 + 0] - mn);
                    float p1 = __expf(sacc[mf][nf][half * 2 + 1] - mn);
                    rs += p0 + p1;
                    uint16_t h0, l0, h1, l1;
                    split_bf16(p0, h0, l0); split_bf16(p1, h1, l1);
                    int o = rowl * AV_STR + wn * 8 + nf * 4 + tq;
                    Ph[o] = pack2(h0, h1);
                    Pl[o] = pack2(l0, l1);
                }
                rs += __shfl_xor_sync(0xffffffffu, rs, 1);
                rs += __shfl_xor_sync(0xffffffffu, rs, 2);
                if (tq == 0) red[wn * 64 + rowl] = rs;
            }
        __syncthreads();   // E

        if (wid < 2 && tq == 0) {
#pragma unroll
            for (int mf = 0; mf < 2; mf++)
#pragma unroll
                for (int half = 0; half < 2; half++) {
                    int rowl = wid * 32 + mf * 16 + quad + half * 8;
                    l_s[rowl] = l_s[rowl] * corr_s[rowl] +
                                red[rowl] + red[64 + rowl] + red[128 + rowl] + red[192 + rowl];
                }
        }
#pragma unroll
        for (int mf = 0; mf < 2; mf++) {
            int r0 = wm * 32 + mf * 16 + quad;
            float c0 = corr_s[r0], c1 = corr_s[r0 + 8];
#pragma unroll
            for (int nf = 0; nf < 8; nf++) {
                oacc[mf][nf][0] *= c0; oacc[mf][nf][1] *= c0;
                oacc[mf][nf][2] *= c1; oacc[mf][nf][3] *= c1;
            }
        }
        CP_WAIT0();
        __syncthreads();   // F

        // ---- O += P V (ldmatrix + split MMA) ----
#pragma unroll
        for (int kk = 0; kk < 4; kk++) {
            const int kb = kk * 8;
            uint32_t pah[2][4], pal[2][4];
#pragma unroll
            for (int mf = 0; mf < 2; mf++) {
                uint32_t ar = sb + (uint32_t)(OFF_PH + (wm*32 + mf*16 + a_ro) * AV_STR + kb + a_ko) * 4u;
                LDSM4(pah[mf][0], pah[mf][1], pah[mf][2], pah[mf][3], ar);
                LDSM4(pal[mf][0], pal[mf][1], pal[mf][2], pal[mf][3], ar + (OFF_PL - OFF_PH) * 4u);
            }
#pragma unroll
            for (int g = 0; g < 4; g++) {
                uint32_t br = sb + (uint32_t)(OFF_KVH + (wn*64 + (2*g + b_go)*8 + jr) * AV_STR + kb + b_ko) * 4u;
                uint32_t v0h[2], v1h[2], v0l[2], v1l[2];
                LDSM4(v0h[0], v0h[1], v1h[0], v1h[1], br);
                LDSM4(v0l[0], v0l[1], v1l[0], v1l[1], br + (OFF_KVL - OFF_KVH) * 4u);
#pragma unroll
                for (int mf = 0; mf < 2; mf++) {
                    MMA_BF16(oacc[mf][2*g],   pah[mf], v0h);
                    MMA_BF16(oacc[mf][2*g],   pah[mf], v0l);
                    MMA_BF16(oacc[mf][2*g],   pal[mf], v0h);
                    MMA_BF16(oacc[mf][2*g+1], pah[mf], v1h);
                    MMA_BF16(oacc[mf][2*g+1], pah[mf], v1l);
                    MMA_BF16(oacc[mf][2*g+1], pal[mf], v1h);
                }
            }
        }
    }

    // ---- epilogue: write ao directly as packed bf16x2 hi/lo ----
#pragma unroll
    for (int mf = 0; mf < 2; mf++) {
        int r0 = wm * 32 + mf * 16 + quad;
        float i0 = 1.f / l_s[r0], i1 = 1.f / l_s[r0 + 8];
        size_t base0 = ((size_t)(b * T_SEQ + q0 + r0)) * (CDIM / 2) + h * (HD / 2);
        size_t base1 = base0 + 8 * (CDIM / 2);
#pragma unroll
        for (int nf = 0; nf < 8; nf++) {
            int cp_ = wn * 32 + nf * 4 + tq;
            uint16_t h0, l0, h1, l1;
            split_bf16(oacc[mf][nf][0] * i0, h0, l0);
            split_bf16(oacc[mf][nf][1] * i0, h1, l1);
            Oh[base0 + cp_] = pack2(h0, h1);
            Ol[base0 + cp_] = pack2(l0, l1);
            split_bf16(oacc[mf][nf][2] * i1, h0, l0);
            split_bf16(oacc[mf][nf][3] * i1, h1, l1);
            Oh[base1 + cp_] = pack2(h0, h1);
            Ol[base1 + cp_] = pack2(l0, l1);
        }
    }
}

// ---------------- launch ----------------
extern "C" void kernel_launch(void* const* d_in, const int* in_sizes, int n_in,
                              void* d_out, int out_size)
{
    const float* x  = (const float*)d_in[0];
    const float* Wq = (const float*)d_in[1];
    const float* Wk = (const float*)d_in[2];
    const float* Wv = (const float*)d_in[3];
    const float* Wo = (const float*)d_in[4];
    const float* qg = (const float*)d_in[5];
    const float* kg = (const float*)d_in[6];
    float* out = (float*)d_out;

    float *q, *k, *v;
    uint32_t *xh, *xl, *aoh, *aol, *wqh, *wql, *wkh, *wkl, *wvh, *wvl, *woh, *wol;
    uint32_t *qph, *qpl, *kph, *kpl, *vth, *vtl;
    cudaGetSymbolAddress((void**)&q,   g_q);
    cudaGetSymbolAddress((void**)&k,   g_k);
    cudaGetSymbolAddress((void**)&v,   g_v);
    cudaGetSymbolAddress((void**)&xh,  g_xh);
    cudaGetSymbolAddress((void**)&xl,  g_xl);
    cudaGetSymbolAddress((void**)&aoh, g_aoh);
    cudaGetSymbolAddress((void**)&aol, g_aol);
    cudaGetSymbolAddress((void**)&wqh, g_wqh);
    cudaGetSymbolAddress((void**)&wql, g_wql);
    cudaGetSymbolAddress((void**)&wkh, g_wkh);
    cudaGetSymbolAddress((void**)&wkl, g_wkl);
    cudaGetSymbolAddress((void**)&wvh, g_wvh);
    cudaGetSymbolAddress((void**)&wvl, g_wvl);
    cudaGetSymbolAddress((void**)&woh, g_woh);
    cudaGetSymbolAddress((void**)&wol, g_wol);
    cudaGetSymbolAddress((void**)&qph, g_qph);
    cudaGetSymbolAddress((void**)&qpl, g_qpl);
    cudaGetSymbolAddress((void**)&kph, g_kph);
    cudaGetSymbolAddress((void**)&kpl, g_kpl);
    cudaGetSymbolAddress((void**)&vth, g_vth);
    cudaGetSymbolAddress((void**)&vtl, g_vtl);

    const int M = BATCH * T_SEQ;   // 8192

    init_invf<<<1, 128>>>();

    split_pack<<<(M * CDIM / 8 + 255) / 256, 256>>>(x,  xh,  xl,  M * CDIM / 8);
    split_pack<<<(CDIM * CDIM / 8 + 255) / 256, 256>>>(Wq, wqh, wql, CDIM * CDIM / 8);
    split_pack<<<(HD * CDIM / 8 + 255) / 256, 256>>>(Wk, wkh, wkl, HD * CDIM / 8);
    split_pack<<<(HD * CDIM / 8 + 255) / 256, 256>>>(Wv, wvh, wvl, HD * CDIM / 8);
    split_pack<<<(CDIM * CDIM / 8 + 255) / 256, 256>>>(Wo, woh, wol, CDIM * CDIM / 8);

    cudaFuncSetAttribute(gemm_bf16_packed, cudaFuncAttributeMaxDynamicSharedMemorySize, GEMM_SMEM);

    gemm_bf16_packed<<<dim3(CDIM / 128, M / 128, 1), 256, GEMM_SMEM>>>(
        M, CDIM, CDIM, xh, xl, wqh, wql, wqh, wql, q, q);
    gemm_bf16_packed<<<dim3(HD / 128, M / 128, 2), 256, GEMM_SMEM>>>(
        M, HD, CDIM, xh, xl, wkh, wkl, wvh, wvl, k, v);

    rmsnorm_rope_pack<<<(M * NH) / 8, 256>>>(q, qg, qph, qpl, M * NH, NH);
    rmsnorm_rope_pack<<<M / 8, 256>>>(k, kg, kph, kpl, M, 1);

    cudaFuncSetAttribute(transpose_split_v, cudaFuncAttributeMaxDynamicSharedMemorySize, VT_SMEM);
    transpose_split_v<<<dim3(T_SEQ / 64, BATCH), 256, VT_SMEM>>>(v, vth, vtl);

    cudaFuncSetAttribute(attn_swa_mma, cudaFuncAttributeMaxDynamicSharedMemorySize, ATTN_SMEM);
    attn_swa_mma<<<BATCH * NH * (T_SEQ / 64), 256, ATTN_SMEM>>>(
        qph, qpl, kph, kpl, vth, vtl, aoh, aol);

    gemm_bf16_packed<<<dim3(CDIM / 128, M / 128, 1), 256, GEMM_SMEM>>>(
        M, CDIM, CDIM, aoh, aol, woh, wol, woh, wol, out, out);
}

// round 9
// speedup vs baseline: 4.1388x; 1.0475x over previous
#include <cuda_runtime.h>
#include <math.h>
#include <stdint.h>

#define T_SEQ 4096
#define BATCH 2
#define CDIM  1024
#define HD    256
#define NH    4
#define WIN   512

// ---------------- scratch (static device globals; no allocation) ----------------
__device__ float    g_q [(size_t)BATCH * T_SEQ * CDIM];
__device__ float    g_k [(size_t)BATCH * T_SEQ * HD];
__device__ float    g_v [(size_t)BATCH * T_SEQ * HD];
__device__ float    g_invf[HD / 2];
// packed bf16x2 hi/lo operand buffers
__device__ uint32_t g_xh [(size_t)BATCH * T_SEQ * CDIM / 2];
__device__ uint32_t g_xl [(size_t)BATCH * T_SEQ * CDIM / 2];
__device__ uint32_t g_aoh[(size_t)BATCH * T_SEQ * CDIM / 2];
__device__ uint32_t g_aol[(size_t)BATCH * T_SEQ * CDIM / 2];
__device__ uint32_t g_wqh[CDIM * CDIM / 2];
__device__ uint32_t g_wql[CDIM * CDIM / 2];
__device__ uint32_t g_wkh[HD * CDIM / 2];
__device__ uint32_t g_wkl[HD * CDIM / 2];
__device__ uint32_t g_wvh[HD * CDIM / 2];
__device__ uint32_t g_wvl[HD * CDIM / 2];
__device__ uint32_t g_woh[CDIM * CDIM / 2];
__device__ uint32_t g_wol[CDIM * CDIM / 2];
// pre-split attention operands
__device__ uint32_t g_qph[(size_t)BATCH * T_SEQ * CDIM / 2];
__device__ uint32_t g_qpl[(size_t)BATCH * T_SEQ * CDIM / 2];
__device__ uint32_t g_kph[(size_t)BATCH * T_SEQ * HD / 2];
__device__ uint32_t g_kpl[(size_t)BATCH * T_SEQ * HD / 2];
__device__ uint32_t g_vth[(size_t)BATCH * HD * T_SEQ / 2];
__device__ uint32_t g_vtl[(size_t)BATCH * HD * T_SEQ / 2];

// ---------------- RoPE inv_freq table ----------------
__global__ void init_invf()
{
    int i = threadIdx.x;
    float e = (float)(2 * i) * (1.0f / HD);
    g_invf[i] = (float)pow(1000000.0, -(double)e);
}

// ---------------- common helpers ----------------
__device__ __forceinline__ void split_bf16(float x, uint16_t& h, uint16_t& l) {
    asm("cvt.rn.bf16.f32 %0, %1;" : "=h"(h) : "f"(x));
    float r = x - __uint_as_float((uint32_t)h << 16);   // exact
    asm("cvt.rn.bf16.f32 %0, %1;" : "=h"(l) : "f"(r));
}
__device__ __forceinline__ uint32_t pack2(uint16_t a, uint16_t b) {
    return (uint32_t)a | ((uint32_t)b << 16);
}
__device__ __forceinline__ uint32_t smem_u32p(const void* p) {
    uint32_t a;
    asm("{ .reg .u64 t; cvta.to.shared.u64 t, %1; cvt.u32.u64 %0, t; }" : "=r"(a) : "l"(p));
    return a;
}

#define MMA_BF16(d, a, b) \
    asm volatile("mma.sync.aligned.m16n8k16.row.col.f32.bf16.bf16.f32 " \
        "{%0,%1,%2,%3}, {%4,%5,%6,%7}, {%8,%9}, {%0,%1,%2,%3};" \
        : "+f"((d)[0]), "+f"((d)[1]), "+f"((d)[2]), "+f"((d)[3]) \
        : "r"((a)[0]), "r"((a)[1]), "r"((a)[2]), "r"((a)[3]), \
          "r"((b)[0]), "r"((b)[1]))

#define LDSM4(r0, r1, r2, r3, a) \
    asm volatile("ldmatrix.sync.aligned.m8n8.x4.shared.b16 {%0,%1,%2,%3}, [%4];" \
        : "=r"(r0), "=r"(r1), "=r"(r2), "=r"(r3) : "r"(a))

__device__ __forceinline__ void cpa16(uint32_t sa, const void* ga) {
    asm volatile("cp.async.cg.shared.global [%0], [%1], 16;" :: "r"(sa), "l"(ga));
}
#define CP_COMMIT() asm volatile("cp.async.commit_group;" ::: "memory")
#define CP_WAIT0()  asm volatile("cp.async.wait_group 0;" ::: "memory")

// ---------------- fp32 -> packed bf16x2 hi/lo split ----------------
__global__ void split_pack(const float* __restrict__ in,
                           uint32_t* __restrict__ oh, uint32_t* __restrict__ ol, int n8)
{
    int i = blockIdx.x * blockDim.x + threadIdx.x;
    if (i >= n8) return;
    float4 a = ((const float4*)in)[2 * i];
    float4 b = ((const float4*)in)[2 * i + 1];
    uint16_t h[8], l[8];
    split_bf16(a.x, h[0], l[0]); split_bf16(a.y, h[1], l[1]);
    split_bf16(a.z, h[2], l[2]); split_bf16(a.w, h[3], l[3]);
    split_bf16(b.x, h[4], l[4]); split_bf16(b.y, h[5], l[5]);
    split_bf16(b.z, h[6], l[6]); split_bf16(b.w, h[7], l[7]);
    ((uint4*)oh)[i] = make_uint4(pack2(h[0],h[1]), pack2(h[2],h[3]), pack2(h[4],h[5]), pack2(h[6],h[7]));
    ((uint4*)ol)[i] = make_uint4(pack2(l[0],l[1]), pack2(l[2],l[3]), pack2(l[4],l[5]), pack2(l[6],l[7]));
}

// ============ packed split-BF16 GEMM, multi-segment N (fused QKV) ============
#define STRP 20
#define PART_U32 (128 * STRP)
#define BUF_U32  (4 * PART_U32)
#define GEMM_SMEM (2 * BUF_U32 * 4)

__global__ __launch_bounds__(256, 2) void gemm_bf16_packed(
    int M, int K, int tiles0, int tiles01,
    const uint32_t* __restrict__ Ah, const uint32_t* __restrict__ Al,
    const uint32_t* __restrict__ Bh0, const uint32_t* __restrict__ Bl0, float* __restrict__ C0, int N0,
    const uint32_t* __restrict__ Bh1, const uint32_t* __restrict__ Bl1, float* __restrict__ C1, int N1,
    const uint32_t* __restrict__ Bh2, const uint32_t* __restrict__ Bl2, float* __restrict__ C2, int N2)
{
    extern __shared__ uint32_t s32[];
    const uint32_t sb = smem_u32p(s32);

    const int nt = blockIdx.x;
    const uint32_t *Bh, *Bl; float* C; int N, ntl;
    if (nt < tiles0)       { Bh = Bh0; Bl = Bl0; C = C0; N = N0; ntl = nt; }
    else if (nt < tiles01) { Bh = Bh1; Bl = Bl1; C = C1; N = N1; ntl = nt - tiles0; }
    else                   { Bh = Bh2; Bl = Bl2; C = C2; N = N2; ntl = nt - tiles01; }

    const int tid    = threadIdx.x;
    const int wid    = tid >> 5;
    const int lane   = tid & 31;
    const int quad   = lane >> 2;
    const int tq     = lane & 3;
    const int warp_m = wid & 3;
    const int warp_n = wid >> 2;
    const int m0 = blockIdx.y << 7;
    const int n0 = ntl << 7;
    const int K2 = K >> 1;

    const int jm   = lane >> 3, jr = lane & 7;
    const int a_ro = (jm & 1) * 8 + jr;
    const int a_ko = (jm >> 1) * 4;
    const int b_go = jm >> 1;
    const int b_ko = (jm & 1) * 4;

    const uint32_t* pAh = Ah + (size_t)m0 * K2;
    const uint32_t* pAl = Al + (size_t)m0 * K2;
    const uint32_t* pBh = Bh + (size_t)n0 * K2;
    const uint32_t* pBl = Bl + (size_t)n0 * K2;

    const int r0_ = tid >> 2;
    const int r1_ = 64 + r0_;
    const int qd  = (tid & 3) * 4;

#define LOADP(it, buf) do { \
    int kp = (it) * 16; \
    uint32_t sbase = sb + (uint32_t)(buf) * BUF_U32 * 4u; \
    cpa16(sbase + (uint32_t)(0*PART_U32 + r0_*STRP + qd)*4u, pAh + (size_t)r0_*K2 + kp + qd); \
    cpa16(sbase + (uint32_t)(0*PART_U32 + r1_*STRP + qd)*4u, pAh + (size_t)r1_*K2 + kp + qd); \
    cpa16(sbase + (uint32_t)(1*PART_U32 + r0_*STRP + qd)*4u, pAl + (size_t)r0_*K2 + kp + qd); \
    cpa16(sbase + (uint32_t)(1*PART_U32 + r1_*STRP + qd)*4u, pAl + (size_t)r1_*K2 + kp + qd); \
    cpa16(sbase + (uint32_t)(2*PART_U32 + r0_*STRP + qd)*4u, pBh + (size_t)r0_*K2 + kp + qd); \
    cpa16(sbase + (uint32_t)(2*PART_U32 + r1_*STRP + qd)*4u, pBh + (size_t)r1_*K2 + kp + qd); \
    cpa16(sbase + (uint32_t)(3*PART_U32 + r0_*STRP + qd)*4u, pBl + (size_t)r0_*K2 + kp + qd); \
    cpa16(sbase + (uint32_t)(3*PART_U32 + r1_*STRP + qd)*4u, pBl + (size_t)r1_*K2 + kp + qd); \
    CP_COMMIT(); \
} while (0)

    float acc[2][8][4];
#pragma unroll
    for (int mf = 0; mf < 2; mf++)
#pragma unroll
        for (int nf = 0; nf < 8; nf++)
#pragma unroll
            for (int r = 0; r < 4; r++) acc[mf][nf][r] = 0.f;

    const int NT = K / 32;

    LOADP(0, 0);

    for (int it = 0; it < NT; ++it) {
        CP_WAIT0();
        __syncthreads();               // single barrier per iter
        if (it + 1 < NT) LOADP(it + 1, (it + 1) & 1);

        const uint32_t sA = sb + (uint32_t)(it & 1) * BUF_U32 * 4u;
        const uint32_t sB = sA + 2u * PART_U32 * 4u;

#pragma unroll
        for (int ks = 0; ks < 2; ks++) {
            const int kb = ks * 8;
            uint32_t ah[2][4], al[2][4];
#pragma unroll
            for (int mf = 0; mf < 2; mf++) {
                uint32_t ar = sA + (uint32_t)((warp_m*32 + mf*16 + a_ro) * STRP + kb + a_ko) * 4u;
                LDSM4(ah[mf][0], ah[mf][1], ah[mf][2], ah[mf][3], ar);
                LDSM4(al[mf][0], al[mf][1], al[mf][2], al[mf][3], ar + PART_U32*4u);
            }
#pragma unroll
            for (int g = 0; g < 4; g++) {
                uint32_t br = sB + (uint32_t)((warp_n*64 + (2*g + b_go)*8 + jr) * STRP + kb + b_ko) * 4u;
                uint32_t b0h[2], b1h[2], b0l[2], b1l[2];
                LDSM4(b0h[0], b0h[1], b1h[0], b1h[1], br);
                LDSM4(b0l[0], b0l[1], b1l[0], b1l[1], br + PART_U32*4u);
#pragma unroll
                for (int mf = 0; mf < 2; mf++) {
                    MMA_BF16(acc[mf][2*g],   ah[mf], b0h);
                    MMA_BF16(acc[mf][2*g],   ah[mf], b0l);
                    MMA_BF16(acc[mf][2*g],   al[mf], b0h);
                    MMA_BF16(acc[mf][2*g+1], ah[mf], b1h);
                    MMA_BF16(acc[mf][2*g+1], ah[mf], b1l);
                    MMA_BF16(acc[mf][2*g+1], al[mf], b1h);
                }
            }
        }
    }

#pragma unroll
    for (int mf = 0; mf < 2; mf++) {
        int row = m0 + warp_m * 32 + mf * 16 + quad;
#pragma unroll
        for (int nf = 0; nf < 8; nf++) {
            int col = n0 + warp_n * 64 + nf * 8 + tq * 2;
            *(float2*)(C + (size_t)row * N + col)       = make_float2(acc[mf][nf][0], acc[mf][nf][1]);
            *(float2*)(C + (size_t)(row + 8) * N + col) = make_float2(acc[mf][nf][2], acc[mf][nf][3]);
        }
    }
#undef LOADP
}

// ---------------- fused RMSNorm + RoPE -> packed bf16x2 hi/lo ----------------
__global__ void rmsnorm_rope_pack(const float* __restrict__ in, const float* __restrict__ gamma,
                                  uint32_t* __restrict__ oh, uint32_t* __restrict__ ol,
                                  int nrows, int heads)
{
    int gw   = (int)((blockIdx.x * blockDim.x + threadIdx.x) >> 5);
    int lane = threadIdx.x & 31;
    if (gw >= nrows) return;
    int bt = gw / heads;
    int t  = bt & (T_SEQ - 1);

    const float* row = in + (size_t)gw * HD;

    float v[8];
    *(float4*)&v[0] = *(const float4*)(row + lane * 8);
    *(float4*)&v[4] = *(const float4*)(row + lane * 8 + 4);

    float ss = 0.f;
#pragma unroll
    for (int i = 0; i < 8; i++) ss += v[i] * v[i];
#pragma unroll
    for (int o = 16; o > 0; o >>= 1) ss += __shfl_xor_sync(0xffffffffu, ss, o);

    float r = rsqrtf(ss * (1.0f / HD) + 1e-6f);

    float g[8];
    *(float4*)&g[0] = *(const float4*)(gamma + lane * 8);
    *(float4*)&g[4] = *(const float4*)(gamma + lane * 8 + 4);

    float invf[4];
    *(float4*)invf = *(const float4*)(g_invf + lane * 4);

    float tf = (float)t;
#pragma unroll
    for (int p = 0; p < 4; p++) {
        float ang = tf * invf[p];
        float c, s;
        sincosf(ang, &s, &c);
        float x0 = v[2 * p]     * r * g[2 * p];
        float x1 = v[2 * p + 1] * r * g[2 * p + 1];
        v[2 * p]     = x0 * c - x1 * s;
        v[2 * p + 1] = x0 * s + x1 * c;
    }

    uint16_t hh[8], ll[8];
#pragma unroll
    for (int i = 0; i < 8; i++) split_bf16(v[i], hh[i], ll[i]);
    size_t ob = (size_t)gw * (HD / 2) + lane * 4;
    *(uint4*)(oh + ob) = make_uint4(pack2(hh[0],hh[1]), pack2(hh[2],hh[3]),
                                    pack2(hh[4],hh[5]), pack2(hh[6],hh[7]));
    *(uint4*)(ol + ob) = make_uint4(pack2(ll[0],ll[1]), pack2(ll[2],ll[3]),
                                    pack2(ll[4],ll[5]), pack2(ll[6],ll[7]));
}

// ---------------- V transpose + split: v[b][t][d] -> Vt[b][d][t-pairs] ----------------
#define VT_SMEM (256 * 69 * 4)
__global__ __launch_bounds__(256) void transpose_split_v(
    const float* __restrict__ v, uint32_t* __restrict__ vth, uint32_t* __restrict__ vtl)
{
    extern __shared__ float st[];
    int b = blockIdx.y, t0 = blockIdx.x * 64;
    int tid = threadIdx.x;
    const float* vb = v + ((size_t)(b * T_SEQ + t0)) * HD;
#pragma unroll
    for (int i = 0; i < 16; i++) {
        int f = i * 256 + tid;
        int t = f >> 6, d4 = (f & 63) * 4;
        float4 x = *(const float4*)(vb + (size_t)t * HD + d4);
        st[(d4 + 0) * 69 + t] = x.x;
        st[(d4 + 1) * 69 + t] = x.y;
        st[(d4 + 2) * 69 + t] = x.z;
        st[(d4 + 3) * 69 + t] = x.w;
    }
    __syncthreads();
    int w = tid >> 5, l = tid & 31;
#pragma unroll
    for (int pass = 0; pass < 32; pass++) {
        int d = pass * 8 + w;
        float x0 = st[d * 69 + 2 * l];
        float x1 = st[d * 69 + 2 * l + 1];
        uint16_t h0, l0, h1, l1;
        split_bf16(x0, h0, l0); split_bf16(x1, h1, l1);
        size_t o = ((size_t)(b * HD + d)) * (T_SEQ / 2) + (t0 >> 1) + l;
        vth[o] = pack2(h0, h1);
        vtl[o] = pack2(l0, l1);
    }
}

// =========== sliding-window flash attention: pre-split operands + ldmatrix ===========
#define AQ_STR 132
#define AV_STR 36
#define OFF_QH   0
#define OFF_QL   (64 * AQ_STR)
#define OFF_KVH  (2 * 64 * AQ_STR)
#define OFF_KVL  (OFF_KVH + 9216)
#define OFF_PH   (OFF_KVL + 9216)
#define OFF_PL   (OFF_PH + 64 * AV_STR)
#define OFF_RED  (OFF_PL + 64 * AV_STR)   // red_max[256]
#define OFF_RED2 (OFF_RED + 256)          // red_sum[256]
#define OFF_MS   (OFF_RED2 + 256)         // m_s[64]
#define OFF_LS   (OFF_MS + 64)            // l_s[64]
#define ATTN_U32 (OFF_LS + 64)
#define ATTN_SMEM (ATTN_U32 * 4)          // ~162 KB

__global__ __launch_bounds__(256, 1) void attn_swa_mma(
    const uint32_t* __restrict__ Qph, const uint32_t* __restrict__ Qpl,
    const uint32_t* __restrict__ Kph, const uint32_t* __restrict__ Kpl,
    const uint32_t* __restrict__ Vth, const uint32_t* __restrict__ Vtl,
    uint32_t* __restrict__ Oh, uint32_t* __restrict__ Ol)
{
    extern __shared__ uint32_t s[];
    const uint32_t sb = smem_u32p(s);
    uint32_t* Ph   = s + OFF_PH;
    uint32_t* Pl   = s + OFF_PL;
    float* red     = (float*)(s + OFF_RED);
    float* red2    = (float*)(s + OFF_RED2);
    float* m_s     = (float*)(s + OFF_MS);
    float* l_s     = (float*)(s + OFF_LS);

    const int tid  = threadIdx.x;
    const int wid  = tid >> 5, lane = tid & 31, quad = lane >> 2, tq = lane & 3;
    const int wm   = wid & 1, wn = wid >> 1;
    const int jm   = lane >> 3, jr = lane & 7;
    const int a_ro = (jm & 1) * 8 + jr;
    const int a_ko = (jm >> 1) * 4;
    const int b_go = jm >> 1;
    const int b_ko = (jm & 1) * 4;
    const int qt   = blockIdx.x & 63;
    const int h    = (blockIdx.x >> 6) & 3;
    const int b    = blockIdx.x >> 8;
    const int q0   = qt << 6;

    const uint32_t* qh_g = Qph + ((size_t)(b * T_SEQ + q0)) * (CDIM / 2) + h * (HD / 2);
    const uint32_t* ql_g = Qpl + ((size_t)(b * T_SEQ + q0)) * (CDIM / 2) + h * (HD / 2);
    const uint32_t* kh_g = Kph + (size_t)b * T_SEQ * (HD / 2);
    const uint32_t* kl_g = Kpl + (size_t)b * T_SEQ * (HD / 2);
    const uint32_t* vh_g = Vth + (size_t)b * HD * (T_SEQ / 2);
    const uint32_t* vl_g = Vtl + (size_t)b * HD * (T_SEQ / 2);

    // ---- Q tile via cp.async ----
#pragma unroll
    for (int i = 0; i < 8; i++) {
        int f = i * 256 + tid, row = f >> 5, c4 = (f & 31) * 4;
        cpa16(sb + (uint32_t)(OFF_QH + row * AQ_STR + c4) * 4u, qh_g + (size_t)row * (CDIM / 2) + c4);
        cpa16(sb + (uint32_t)(OFF_QL + row * AQ_STR + c4) * 4u, ql_g + (size_t)row * (CDIM / 2) + c4);
    }
    CP_COMMIT();
    if (tid < 64) { m_s[tid] = -1e30f; l_s[tid] = 0.f; }
    CP_WAIT0();
    __syncthreads();

    float oacc[2][8][4];
#pragma unroll
    for (int mf = 0; mf < 2; mf++)
#pragma unroll
        for (int nf = 0; nf < 8; nf++)
#pragma unroll
            for (int r = 0; r < 4; r++) oacc[mf][nf][r] = 0.f;

    int kt0 = q0 - WIN; if (kt0 < 0) kt0 = 0;

    for (int kt = kt0; kt <= q0; kt += 64) {
        __syncthreads();   // A: prev PV done reading KV(V)/P

        // ---- K tile via cp.async ----
#pragma unroll
        for (int i = 0; i < 8; i++) {
            int f = i * 256 + tid, row = f >> 5, c4 = (f & 31) * 4;
            cpa16(sb + (uint32_t)(OFF_KVH + row * AQ_STR + c4) * 4u, kh_g + (size_t)(kt + row) * (HD / 2) + c4);
            cpa16(sb + (uint32_t)(OFF_KVL + row * AQ_STR + c4) * 4u, kl_g + (size_t)(kt + row) * (HD / 2) + c4);
        }
        CP_COMMIT();
        CP_WAIT0();
        __syncthreads();   // B

        // ---- S = Q K^T (ldmatrix + split MMA) ----
        float sacc[2][2][4];
#pragma unroll
        for (int mf = 0; mf < 2; mf++)
#pragma unroll
            for (int nf = 0; nf < 2; nf++)
#pragma unroll
                for (int r = 0; r < 4; r++) sacc[mf][nf][r] = 0.f;

#pragma unroll
        for (int ks = 0; ks < 16; ks++) {
            const int kb = ks * 8;
            uint32_t ah[2][4], al[2][4];
#pragma unroll
            for (int mf = 0; mf < 2; mf++) {
                uint32_t ar = sb + (uint32_t)(OFF_QH + (wm*32 + mf*16 + a_ro) * AQ_STR + kb + a_ko) * 4u;
                LDSM4(ah[mf][0], ah[mf][1], ah[mf][2], ah[mf][3], ar);
                LDSM4(al[mf][0], al[mf][1], al[mf][2], al[mf][3], ar + (OFF_QL - OFF_QH) * 4u);
            }
            uint32_t br = sb + (uint32_t)(OFF_KVH + (wn*16 + b_go*8 + jr) * AQ_STR + kb + b_ko) * 4u;
            uint32_t b0h[2], b1h[2], b0l[2], b1l[2];
            LDSM4(b0h[0], b0h[1], b1h[0], b1h[1], br);
            LDSM4(b0l[0], b0l[1], b1l[0], b1l[1], br + (OFF_KVL - OFF_KVH) * 4u);
#pragma unroll
            for (int mf = 0; mf < 2; mf++) {
                MMA_BF16(sacc[mf][0], ah[mf], b0h);
                MMA_BF16(sacc[mf][0], ah[mf], b0l);
                MMA_BF16(sacc[mf][0], al[mf], b0h);
                MMA_BF16(sacc[mf][1], ah[mf], b1h);
                MMA_BF16(sacc[mf][1], ah[mf], b1l);
                MMA_BF16(sacc[mf][1], al[mf], b1h);
            }
        }

        // ---- mask + scale + row max -> red ----
#pragma unroll
        for (int mf = 0; mf < 2; mf++)
#pragma unroll
            for (int half = 0; half < 2; half++) {
                int rowl = wm * 32 + mf * 16 + quad + half * 8;
                int irow = q0 + rowl;
                float mt = -1e30f;
#pragma unroll
                for (int nf = 0; nf < 2; nf++)
#pragma unroll
                    for (int p = 0; p < 2; p++) {
                        int j = kt + wn * 16 + nf * 8 + tq * 2 + p;
                        bool ok = (j <= irow) && (j >= irow - WIN);
                        float x = ok ? sacc[mf][nf][half * 2 + p] * 0.0625f : -1e30f;
                        sacc[mf][nf][half * 2 + p] = x;
                        mt = fmaxf(mt, x);
                    }
                mt = fmaxf(mt, __shfl_xor_sync(0xffffffffu, mt, 1));
                mt = fmaxf(mt, __shfl_xor_sync(0xffffffffu, mt, 2));
                if (tq == 0) red[wn * 64 + rowl] = mt;
            }
        __syncthreads();   // C

        // ---- V^T tile via cp.async (overlaps softmax) ----
#pragma unroll
        for (int i = 0; i < 8; i++) {
            int f = i * 256 + tid, d = f >> 3, c4 = (f & 7) * 4;
            cpa16(sb + (uint32_t)(OFF_KVH + d * AV_STR + c4) * 4u, vh_g + (size_t)d * (T_SEQ / 2) + (kt >> 1) + c4);
            cpa16(sb + (uint32_t)(OFF_KVL + d * AV_STR + c4) * 4u, vl_g + (size_t)d * (T_SEQ / 2) + (kt >> 1) + c4);
        }
        CP_COMMIT();

        // ---- every thread computes its rows' m/corr locally (identical values) ----
        float mn_loc[2][2], corr_loc[2][2];
#pragma unroll
        for (int mf = 0; mf < 2; mf++)
#pragma unroll
            for (int half = 0; half < 2; half++) {
                int rowl = wm * 32 + mf * 16 + quad + half * 8;
                float mt = fmaxf(fmaxf(red[rowl], red[64 + rowl]),
                                 fmaxf(red[128 + rowl], red[192 + rowl]));
                float mo = m_s[rowl];
                float mn = fmaxf(mo, mt);
                mn_loc[mf][half]   = mn;
                corr_loc[mf][half] = __expf(mo - mn);
            }

        // ---- P = exp(S - m); split -> Ph/Pl; row sums -> red2 ----
#pragma unroll
        for (int mf = 0; mf < 2; mf++)
#pragma unroll
            for (int half = 0; half < 2; half++) {
                int rowl = wm * 32 + mf * 16 + quad + half * 8;
                float mn = mn_loc[mf][half];
                float rs = 0.f;
#pragma unroll
                for (int nf = 0; nf < 2; nf++) {
                    float p0 = __expf(sacc[mf][nf][half * 2 + 0] - mn);
                    float p1 = __expf(sacc[mf][nf][half * 2 + 1] - mn);
                    rs += p0 + p1;
                    uint16_t h0, l0, h1, l1;
                    split_bf16(p0, h0, l0); split_bf16(p1, h1, l1);
                    int o = rowl * AV_STR + wn * 8 + nf * 4 + tq;
                    Ph[o] = pack2(h0, h1);
                    Pl[o] = pack2(l0, l1);
                }
                rs += __shfl_xor_sync(0xffffffffu, rs, 1);
                rs += __shfl_xor_sync(0xffffffffu, rs, 2);
                if (tq == 0) red2[wn * 64 + rowl] = rs;
            }
        __syncthreads();   // E

        // ---- writers update running l/m; all threads rescale accumulators ----
        if (wid < 2 && tq == 0) {
#pragma unroll
            for (int mf = 0; mf < 2; mf++)
#pragma unroll
                for (int half = 0; half < 2; half++) {
                    int rowl = wid * 32 + mf * 16 + quad + half * 8;
                    l_s[rowl] = l_s[rowl] * corr_loc[mf][half] +
                                red2[rowl] + red2[64 + rowl] + red2[128 + rowl] + red2[192 + rowl];
                    m_s[rowl] = mn_loc[mf][half];
                }
        }
#pragma unroll
        for (int mf = 0; mf < 2; mf++) {
            float c0 = corr_loc[mf][0], c1 = corr_loc[mf][1];
#pragma unroll
            for (int nf = 0; nf < 8; nf++) {
                oacc[mf][nf][0] *= c0; oacc[mf][nf][1] *= c0;
                oacc[mf][nf][2] *= c1; oacc[mf][nf][3] *= c1;
            }
        }
        CP_WAIT0();
        __syncthreads();   // F

        // ---- O += P V (ldmatrix + split MMA) ----
#pragma unroll
        for (int kk = 0; kk < 4; kk++) {
            const int kb = kk * 8;
            uint32_t pah[2][4], pal[2][4];
#pragma unroll
            for (int mf = 0; mf < 2; mf++) {
                uint32_t ar = sb + (uint32_t)(OFF_PH + (wm*32 + mf*16 + a_ro) * AV_STR + kb + a_ko) * 4u;
                LDSM4(pah[mf][0], pah[mf][1], pah[mf][2], pah[mf][3], ar);
                LDSM4(pal[mf][0], pal[mf][1], pal[mf][2], pal[mf][3], ar + (OFF_PL - OFF_PH) * 4u);
            }
#pragma unroll
            for (int g = 0; g < 4; g++) {
                uint32_t br = sb + (uint32_t)(OFF_KVH + (wn*64 + (2*g + b_go)*8 + jr) * AV_STR + kb + b_ko) * 4u;
                uint32_t v0h[2], v1h[2], v0l[2], v1l[2];
                LDSM4(v0h[0], v0h[1], v1h[0], v1h[1], br);
                LDSM4(v0l[0], v0l[1], v1l[0], v1l[1], br + (OFF_KVL - OFF_KVH) * 4u);
#pragma unroll
                for (int mf = 0; mf < 2; mf++) {
                    MMA_BF16(oacc[mf][2*g],   pah[mf], v0h);
                    MMA_BF16(oacc[mf][2*g],   pah[mf], v0l);
                    MMA_BF16(oacc[mf][2*g],   pal[mf], v0h);
                    MMA_BF16(oacc[mf][2*g+1], pah[mf], v1h);
                    MMA_BF16(oacc[mf][2*g+1], pah[mf], v1l);
                    MMA_BF16(oacc[mf][2*g+1], pal[mf], v1h);
                }
            }
        }
    }

    // ---- epilogue: write ao directly as packed bf16x2 hi/lo ----
#pragma unroll
    for (int mf = 0; mf < 2; mf++) {
        int r0 = wm * 32 + mf * 16 + quad;
        float i0 = 1.f / l_s[r0], i1 = 1.f / l_s[r0 + 8];
        size_t base0 = ((size_t)(b * T_SEQ + q0 + r0)) * (CDIM / 2) + h * (HD / 2);
        size_t base1 = base0 + 8 * (CDIM / 2);
#pragma unroll
        for (int nf = 0; nf < 8; nf++) {
            int cp_ = wn * 32 + nf * 4 + tq;
            uint16_t h0, l0, h1, l1;
            split_bf16(oacc[mf][nf][0] * i0, h0, l0);
            split_bf16(oacc[mf][nf][1] * i0, h1, l1);
            Oh[base0 + cp_] = pack2(h0, h1);
            Ol[base0 + cp_] = pack2(l0, l1);
            split_bf16(oacc[mf][nf][2] * i1, h0, l0);
            split_bf16(oacc[mf][nf][3] * i1, h1, l1);
            Oh[base1 + cp_] = pack2(h0, h1);
            Ol[base1 + cp_] = pack2(l0, l1);
        }
    }
}

// ---------------- launch ----------------
extern "C" void kernel_launch(void* const* d_in, const int* in_sizes, int n_in,
                              void* d_out, int out_size)
{
    const float* x  = (const float*)d_in[0];
    const float* Wq = (const float*)d_in[1];
    const float* Wk = (const float*)d_in[2];
    const float* Wv = (const float*)d_in[3];
    const float* Wo = (const float*)d_in[4];
    const float* qg = (const float*)d_in[5];
    const float* kg = (const float*)d_in[6];
    float* out = (float*)d_out;

    float *q, *k, *v;
    uint32_t *xh, *xl, *aoh, *aol, *wqh, *wql, *wkh, *wkl, *wvh, *wvl, *woh, *wol;
    uint32_t *qph, *qpl, *kph, *kpl, *vth, *vtl;
    cudaGetSymbolAddress((void**)&q,   g_q);
    cudaGetSymbolAddress((void**)&k,   g_k);
    cudaGetSymbolAddress((void**)&v,   g_v);
    cudaGetSymbolAddress((void**)&xh,  g_xh);
    cudaGetSymbolAddress((void**)&xl,  g_xl);
    cudaGetSymbolAddress((void**)&aoh, g_aoh);
    cudaGetSymbolAddress((void**)&aol, g_aol);
    cudaGetSymbolAddress((void**)&wqh, g_wqh);
    cudaGetSymbolAddress((void**)&wql, g_wql);
    cudaGetSymbolAddress((void**)&wkh, g_wkh);
    cudaGetSymbolAddress((void**)&wkl, g_wkl);
    cudaGetSymbolAddress((void**)&wvh, g_wvh);
    cudaGetSymbolAddress((void**)&wvl, g_wvl);
    cudaGetSymbolAddress((void**)&woh, g_woh);
    cudaGetSymbolAddress((void**)&wol, g_wol);
    cudaGetSymbolAddress((void**)&qph, g_qph);
    cudaGetSymbolAddress((void**)&qpl, g_qpl);
    cudaGetSymbolAddress((void**)&kph, g_kph);
    cudaGetSymbolAddress((void**)&kpl, g_kpl);
    cudaGetSymbolAddress((void**)&vth, g_vth);
    cudaGetSymbolAddress((void**)&vtl, g_vtl);

    const int M = BATCH * T_SEQ;   // 8192

    init_invf<<<1, 128>>>();

    split_pack<<<(M * CDIM / 8 + 255) / 256, 256>>>(x,  xh,  xl,  M * CDIM / 8);
    split_pack<<<(CDIM * CDIM / 8 + 255) / 256, 256>>>(Wq, wqh, wql, CDIM * CDIM / 8);
    split_pack<<<(HD * CDIM / 8 + 255) / 256, 256>>>(Wk, wkh, wkl, HD * CDIM / 8);
    split_pack<<<(HD * CDIM / 8 + 255) / 256, 256>>>(Wv, wvh, wvl, HD * CDIM / 8);
    split_pack<<<(CDIM * CDIM / 8 + 255) / 256, 256>>>(Wo, woh, wol, CDIM * CDIM / 8);

    cudaFuncSetAttribute(gemm_bf16_packed, cudaFuncAttributeMaxDynamicSharedMemorySize, GEMM_SMEM);

    // fused Q+K+V projection: n-tiles 0-7 -> Wq/q, 8-9 -> Wk/k, 10-11 -> Wv/v
    gemm_bf16_packed<<<dim3(12, M / 128), 256, GEMM_SMEM>>>(
        M, CDIM, 8, 10, xh, xl,
        wqh, wql, q, CDIM,
        wkh, wkl, k, HD,
        wvh, wvl, v, HD);

    rmsnorm_rope_pack<<<(M * NH) / 8, 256>>>(q, qg, qph, qpl, M * NH, NH);
    rmsnorm_rope_pack<<<M / 8, 256>>>(k, kg, kph, kpl, M, 1);

    cudaFuncSetAttribute(transpose_split_v, cudaFuncAttributeMaxDynamicSharedMemorySize, VT_SMEM);
    transpose_split_v<<<dim3(T_SEQ / 64, BATCH), 256, VT_SMEM>>>(v, vth, vtl);

    cudaFuncSetAttribute(attn_swa_mma, cudaFuncAttributeMaxDynamicSharedMemorySize, ATTN_SMEM);
    attn_swa_mma<<<BATCH * NH * (T_SEQ / 64), 256, ATTN_SMEM>>>(
        qph, qpl, kph, kpl, vth, vtl, aoh, aol);

    // output projection
    gemm_bf16_packed<<<dim3(8, M / 128), 256, GEMM_SMEM>>>(
        M, CDIM, 8, 8, aoh, aol,
        woh, wol, out, CDIM,
        woh, wol, out, CDIM,
        woh, wol, out, CDIM);
}